// round 1
// baseline (speedup 1.0000x reference)
#include <cuda_runtime.h>
#include <math.h>

#define N_TOK 8192
#define DIM   512
#define GN_EPS 1e-5f

// ---------------- scratch (static device arrays; runtime alloc is forbidden) ----------------
__device__ float g_Q[(size_t)N_TOK * DIM];
__device__ float g_K[(size_t)N_TOK * DIM];
__device__ float g_V[(size_t)N_TOK * DIM];
__device__ float g_S[(size_t)N_TOK * N_TOK];   // 256 MB retention matrix scratch
__device__ float g_X[(size_t)N_TOK * DIM];
__device__ float g_H[(size_t)N_TOK * DIM];

// ---------------- tiled SGEMM ----------------
// C[M,Nn] = A[M,Kk] @ B  (+ epilogue)
//   TRANSB=false: B is [Kk,Nn] row-major  (NN)
//   TRANSB=true : B is [Nn,Kk] row-major  (NT, C = A @ B^T)
// EPI: 0 = +bias (bias may be null), 1 = gelu(c+bias), 2 = c * Dm[row,col]
template<bool TRANSB, int EPI>
__global__ __launch_bounds__(256, 2)
void gemm_k(const float* __restrict__ A, const float* __restrict__ B,
            const float* __restrict__ bias, const float* __restrict__ Dm,
            float* __restrict__ C, int M, int Nn, int Kk)
{
    constexpr int BM = 128, BN = 128, BK = 16;
    __shared__ float As[BK][BM + 4];   // transposed A tile, padded
    __shared__ float Bs[BK][BN + 4];   // B tile, padded

    const int t  = threadIdx.x;
    const int tx = t & 15;             // 0..15 -> output col group
    const int ty = t >> 4;             // 0..15 -> output row group
    const int br = blockIdx.y;
    const int bc = blockIdx.x;

    const float* Ab = A + (size_t)br * BM * Kk;

    float acc[8][8];
    #pragma unroll
    for (int i = 0; i < 8; i++)
        #pragma unroll
        for (int j = 0; j < 8; j++) acc[i][j] = 0.f;

    for (int k0 = 0; k0 < Kk; k0 += BK) {
        // ---- load A tile (BM x BK) -> As[k][m] (transposed), 512 float4 total ----
        #pragma unroll
        for (int q = 0; q < 2; q++) {
            int f  = t + q * 256;          // 0..511
            int ar = f >> 2;               // row in tile 0..127
            int ac = (f & 3) * 4;          // k offset 0,4,8,12
            const float4 v = *(const float4*)(Ab + (size_t)ar * Kk + k0 + ac);
            As[ac + 0][ar] = v.x; As[ac + 1][ar] = v.y;
            As[ac + 2][ar] = v.z; As[ac + 3][ar] = v.w;
        }
        // ---- load B tile -> Bs[k][n] ----
        if (!TRANSB) {
            #pragma unroll
            for (int q = 0; q < 2; q++) {
                int f   = t + q * 256;
                int brw = f >> 5;          // k row 0..15
                int bcl = (f & 31) * 4;    // col 0..124
                const float4 v = *(const float4*)(B + (size_t)(k0 + brw) * Nn + bc * BN + bcl);
                *(float4*)&Bs[brw][bcl] = v;
            }
        } else {
            #pragma unroll
            for (int q = 0; q < 2; q++) {
                int f  = t + q * 256;
                int jr = f >> 2;           // n row in tile 0..127
                int kc = (f & 3) * 4;      // k offset
                const float4 v = *(const float4*)(B + (size_t)(bc * BN + jr) * Kk + k0 + kc);
                Bs[kc + 0][jr] = v.x; Bs[kc + 1][jr] = v.y;
                Bs[kc + 2][jr] = v.z; Bs[kc + 3][jr] = v.w;
            }
        }
        __syncthreads();

        // ---- 128x128x16 compute, 8x8 per thread ----
        #pragma unroll
        for (int kk = 0; kk < BK; kk++) {
            float ra[8], rb[8];
            #pragma unroll
            for (int i = 0; i < 8; i++) ra[i] = As[kk][ty * 8 + i];
            #pragma unroll
            for (int j = 0; j < 8; j++) rb[j] = Bs[kk][tx * 8 + j];
            #pragma unroll
            for (int i = 0; i < 8; i++)
                #pragma unroll
                for (int j = 0; j < 8; j++)
                    acc[i][j] = fmaf(ra[i], rb[j], acc[i][j]);
        }
        __syncthreads();
    }

    // ---- epilogue ----
    #pragma unroll
    for (int i = 0; i < 8; i++) {
        const int row = br * BM + ty * 8 + i;
        #pragma unroll
        for (int j = 0; j < 8; j++) {
            const int col = bc * BN + tx * 8 + j;
            float c = acc[i][j];
            if (EPI == 2) {
                c *= Dm[(size_t)row * Nn + col];
            } else {
                if (bias) c += bias[col];
                if (EPI == 1) c = 0.5f * c * (1.f + erff(c * 0.70710678118654752f));
            }
            C[(size_t)row * Nn + col] = c;
        }
    }
}

// ---------------- GroupNorm (16 groups of 32 channels, one warp per group) ----------------
__global__ void groupnorm_k(float* __restrict__ io,
                            const float* __restrict__ gamma,
                            const float* __restrict__ beta)
{
    const int row = blockIdx.x;
    const int c   = threadIdx.x;       // 0..511, warp == one 32-channel group
    float v  = io[(size_t)row * DIM + c];
    float s  = v;
    float s2 = v * v;
    #pragma unroll
    for (int off = 16; off > 0; off >>= 1) {
        s  += __shfl_xor_sync(0xffffffffu, s,  off);
        s2 += __shfl_xor_sync(0xffffffffu, s2, off);
    }
    const float mu  = s * (1.f / 32.f);
    const float var = s2 * (1.f / 32.f) - mu * mu;
    io[(size_t)row * DIM + c] = (v - mu) * rsqrtf(var + GN_EPS) * gamma[c] + beta[c];
}

// ---------------- launch ----------------
extern "C" void kernel_launch(void* const* d_in, const int* in_sizes, int n_in,
                              void* d_out, int out_size)
{
    const float* x     = (const float*)d_in[0];
    const float* D     = (const float*)d_in[1];
    const float* Wq    = (const float*)d_in[2];
    const float* bq    = (const float*)d_in[3];
    const float* Wk    = (const float*)d_in[4];
    const float* bk    = (const float*)d_in[5];
    const float* Wv    = (const float*)d_in[6];
    const float* bv    = (const float*)d_in[7];
    const float* Wf    = (const float*)d_in[8];
    const float* bf    = (const float*)d_in[9];
    const float* Wp    = (const float*)d_in[10];
    const float* bp    = (const float*)d_in[11];
    const float* gamma = (const float*)d_in[12];
    const float* beta  = (const float*)d_in[13];
    float* out = (float*)d_out;

    float *Q, *K, *V, *S, *X, *H;
    cudaGetSymbolAddress((void**)&Q, g_Q);
    cudaGetSymbolAddress((void**)&K, g_K);
    cudaGetSymbolAddress((void**)&V, g_V);
    cudaGetSymbolAddress((void**)&S, g_S);
    cudaGetSymbolAddress((void**)&X, g_X);
    cudaGetSymbolAddress((void**)&H, g_H);

    dim3 blk(256);
    dim3 g_thin(DIM / 128, N_TOK / 128);     // 4 x 64
    dim3 g_fat (N_TOK / 128, N_TOK / 128);   // 64 x 64

    // Q/K/V projections
    gemm_k<false, 0><<<g_thin, blk>>>(x, Wq, bq, nullptr, Q, N_TOK, DIM, DIM);
    gemm_k<false, 0><<<g_thin, blk>>>(x, Wk, bk, nullptr, K, N_TOK, DIM, DIM);
    gemm_k<false, 0><<<g_thin, blk>>>(x, Wv, bv, nullptr, V, N_TOK, DIM, DIM);
    // S = D .* (Q @ K^T)
    gemm_k<true, 2><<<g_fat, blk>>>(Q, K, nullptr, D, S, N_TOK, N_TOK, DIM);
    // X = S @ V
    gemm_k<false, 0><<<g_thin, blk>>>(S, V, nullptr, nullptr, X, N_TOK, DIM, N_TOK);
    // H = gelu(X @ Wf + bf)
    gemm_k<false, 1><<<g_thin, blk>>>(X, Wf, bf, nullptr, H, N_TOK, DIM, DIM);
    // out_pre = H @ Wp + bp  (straight into d_out)
    gemm_k<false, 0><<<g_thin, blk>>>(H, Wp, bp, nullptr, out, N_TOK, DIM, DIM);
    // in-place group norm
    groupnorm_k<<<N_TOK, DIM>>>(out, gamma, beta);
}

// round 2
// speedup vs baseline: 3.0386x; 3.0386x over previous
#include <cuda_runtime.h>
#include <math.h>
#include <stdint.h>

#define N_TOK 8192
#define DIM   512
#define GN_EPS 1e-5f

// ---------------- scratch (static device arrays; runtime alloc is forbidden) ----------------
__device__ float g_Q[(size_t)N_TOK * DIM];
__device__ float g_K[(size_t)N_TOK * DIM];
__device__ float g_V[(size_t)N_TOK * DIM];
__device__ float g_S[(size_t)N_TOK * N_TOK];   // 256 MB retention matrix scratch
__device__ float g_X[(size_t)N_TOK * DIM];
__device__ float g_H[(size_t)N_TOK * DIM];

// ---------------- helpers ----------------
__device__ __forceinline__ uint32_t f2tf32(float f) {
    uint32_t r;
    asm("cvt.rna.tf32.f32 %0, %1;" : "=r"(r) : "f"(f));
    return r;
}

__device__ __forceinline__ uint32_t smem_u32(const void* p) {
    return (uint32_t)__cvta_generic_to_shared(p);
}

__device__ __forceinline__ void ldmatrix_x4(uint32_t& r0, uint32_t& r1, uint32_t& r2, uint32_t& r3,
                                            uint32_t addr) {
    asm volatile("ldmatrix.sync.aligned.m8n8.x4.shared.b16 {%0,%1,%2,%3}, [%4];"
                 : "=r"(r0), "=r"(r1), "=r"(r2), "=r"(r3) : "r"(addr));
}

__device__ __forceinline__ void mma_tf32(float* c, const uint32_t* a, const uint32_t* b) {
    asm volatile("mma.sync.aligned.m16n8k8.row.col.f32.tf32.tf32.f32 "
                 "{%0,%1,%2,%3}, {%4,%5,%6,%7}, {%8,%9}, {%0,%1,%2,%3};"
                 : "+f"(c[0]), "+f"(c[1]), "+f"(c[2]), "+f"(c[3])
                 : "r"(a[0]), "r"(a[1]), "r"(a[2]), "r"(a[3]), "r"(b[0]), "r"(b[1]));
}

// swizzled float-index inside a [rows][32] tile: 8 16B-units per row, unit ^= (row&7)
__device__ __forceinline__ int sidx(int r, int unit) { return r * 32 + ((unit ^ (r & 7)) << 2); }

// ---------------- tf32 tensor-core GEMM ----------------
// C[M,Nn] = A[M,Kk] @ B (+ epilogue)
//   TRANSB=false: B is [Kk,Nn] row-major (NN)
//   TRANSB=true : B is [Nn,Kk] row-major (NT, C = A @ B^T)
// EPI: 0 = +bias (may be null), 1 = gelu(c+bias), 2 = c * Dm[row,col]
template<bool TRANSB, int EPI>
__global__ __launch_bounds__(256)
void gemm_tc(const float* __restrict__ A, const float* __restrict__ B,
             const float* __restrict__ bias, const float* __restrict__ Dm,
             float* __restrict__ C, int M, int Nn, int Kk)
{
    constexpr int BM = 128, BN = 128, BK = 32;
    __shared__ float As[BM * BK];   // [m][k], swizzled units
    __shared__ float Bs[BN * BK];   // [n][k], swizzled units

    const int t    = threadIdx.x;
    const int lane = t & 31;
    const int wid  = t >> 5;
    const int wm   = (wid & 3) * 32;   // warp M offset (4 warps along M)
    const int wn   = (wid >> 2) * 64;  // warp N offset (2 warps along N)
    const int br   = blockIdx.y;
    const int bc   = blockIdx.x;

    float acc[2][8][4];
    #pragma unroll
    for (int i = 0; i < 2; i++)
        #pragma unroll
        for (int j = 0; j < 8; j++)
            #pragma unroll
            for (int q = 0; q < 4; q++) acc[i][j][q] = 0.f;

    // global load indices
    const int ga_m = t >> 3;          // 0..31 (+32 each pass)
    const int ga_u = t & 7;           // 16B unit within row
    const int gb_n = t & 127;         // NN path
    const int gb_q = t >> 7;          // k-quad 0..1 (+2 each pass)

    for (int k0 = 0; k0 < Kk; k0 += BK) {
        // ---- A tile: [m][k] (same path for NT B too) ----
        #pragma unroll
        for (int p = 0; p < 4; p++) {
            const int m = ga_m + p * 32;
            const float4 v = *(const float4*)(A + (size_t)(br * BM + m) * Kk + k0 + ga_u * 4);
            uint4 w = { f2tf32(v.x), f2tf32(v.y), f2tf32(v.z), f2tf32(v.w) };
            *(uint4*)&As[sidx(m, ga_u)] = w;
        }
        // ---- B tile -> Bs[n][k] ----
        if (TRANSB) {
            #pragma unroll
            for (int p = 0; p < 4; p++) {
                const int n = ga_m + p * 32;
                const float4 v = *(const float4*)(B + (size_t)(bc * BN + n) * Kk + k0 + ga_u * 4);
                uint4 w = { f2tf32(v.x), f2tf32(v.y), f2tf32(v.z), f2tf32(v.w) };
                *(uint4*)&Bs[sidx(n, ga_u)] = w;
            }
        } else {
            #pragma unroll
            for (int p = 0; p < 4; p++) {
                const int kq = gb_q + p * 2;          // 0..7
                uint4 w;
                w.x = f2tf32(B[(size_t)(k0 + kq * 4 + 0) * Nn + bc * BN + gb_n]);
                w.y = f2tf32(B[(size_t)(k0 + kq * 4 + 1) * Nn + bc * BN + gb_n]);
                w.z = f2tf32(B[(size_t)(k0 + kq * 4 + 2) * Nn + bc * BN + gb_n]);
                w.w = f2tf32(B[(size_t)(k0 + kq * 4 + 3) * Nn + bc * BN + gb_n]);
                *(uint4*)&Bs[sidx(gb_n, kq)] = w;
            }
        }
        __syncthreads();

        // ---- compute: 4 k-steps of m16n8k8 ----
        #pragma unroll
        for (int ks = 0; ks < 4; ks++) {
            const int ub = ks * 2;                    // base 16B-unit for this k-step
            // A fragments: 2 m-frags of 16 rows
            uint32_t af[2][4];
            #pragma unroll
            for (int mf = 0; mf < 2; mf++) {
                const int j = lane >> 3, r = lane & 7;
                const int row  = wm + mf * 16 + (j & 1) * 8 + r;
                const int unit = ub + (j >> 1);
                ldmatrix_x4(af[mf][0], af[mf][1], af[mf][2], af[mf][3],
                            smem_u32(&As[sidx(row, unit)]));
            }
            // B fragments: 8 n-frags of 8 cols (loaded 2 at a time)
            uint32_t bf[8][2];
            #pragma unroll
            for (int nb = 0; nb < 4; nb++) {
                const int j = lane >> 3, r = lane & 7;
                const int row  = wn + nb * 16 + (j >> 1) * 8 + r;
                const int unit = ub + (j & 1);
                uint32_t r0, r1, r2, r3;
                ldmatrix_x4(r0, r1, r2, r3, smem_u32(&Bs[sidx(row, unit)]));
                bf[nb * 2 + 0][0] = r0; bf[nb * 2 + 0][1] = r1;
                bf[nb * 2 + 1][0] = r2; bf[nb * 2 + 1][1] = r3;
            }
            #pragma unroll
            for (int mf = 0; mf < 2; mf++)
                #pragma unroll
                for (int nf = 0; nf < 8; nf++)
                    mma_tf32(acc[mf][nf], af[mf], bf[nf]);
        }
        __syncthreads();
    }

    // ---- epilogue ----
    const int g = lane >> 2, tg = lane & 3;
    #pragma unroll
    for (int mf = 0; mf < 2; mf++) {
        #pragma unroll
        for (int nf = 0; nf < 8; nf++) {
            const int col = bc * BN + wn + nf * 8 + tg * 2;
            #pragma unroll
            for (int h = 0; h < 2; h++) {          // h=0: rows g, h=1: rows g+8
                const int row = br * BM + wm + mf * 16 + g + h * 8;
                float c0 = acc[mf][nf][h * 2 + 0];
                float c1 = acc[mf][nf][h * 2 + 1];
                if (EPI == 2) {
                    const float2 d = *(const float2*)(Dm + (size_t)row * Nn + col);
                    c0 *= d.x; c1 *= d.y;
                } else {
                    if (bias) { c0 += bias[col]; c1 += bias[col + 1]; }
                    if (EPI == 1) {
                        c0 = 0.5f * c0 * (1.f + erff(c0 * 0.70710678118654752f));
                        c1 = 0.5f * c1 * (1.f + erff(c1 * 0.70710678118654752f));
                    }
                }
                float2 o = { c0, c1 };
                *(float2*)(C + (size_t)row * Nn + col) = o;
            }
        }
    }
}

// ---------------- GroupNorm (16 groups of 32 channels, one warp per group) ----------------
__global__ void groupnorm_k(float* __restrict__ io,
                            const float* __restrict__ gamma,
                            const float* __restrict__ beta)
{
    const int row = blockIdx.x;
    const int c   = threadIdx.x;
    float v  = io[(size_t)row * DIM + c];
    float s  = v;
    float s2 = v * v;
    #pragma unroll
    for (int off = 16; off > 0; off >>= 1) {
        s  += __shfl_xor_sync(0xffffffffu, s,  off);
        s2 += __shfl_xor_sync(0xffffffffu, s2, off);
    }
    const float mu  = s * (1.f / 32.f);
    const float var = s2 * (1.f / 32.f) - mu * mu;
    io[(size_t)row * DIM + c] = (v - mu) * rsqrtf(var + GN_EPS) * gamma[c] + beta[c];
}

// ---------------- launch ----------------
extern "C" void kernel_launch(void* const* d_in, const int* in_sizes, int n_in,
                              void* d_out, int out_size)
{
    const float* x     = (const float*)d_in[0];
    const float* D     = (const float*)d_in[1];
    const float* Wq    = (const float*)d_in[2];
    const float* bq    = (const float*)d_in[3];
    const float* Wk    = (const float*)d_in[4];
    const float* bk    = (const float*)d_in[5];
    const float* Wv    = (const float*)d_in[6];
    const float* bv    = (const float*)d_in[7];
    const float* Wf    = (const float*)d_in[8];
    const float* bf    = (const float*)d_in[9];
    const float* Wp    = (const float*)d_in[10];
    const float* bp    = (const float*)d_in[11];
    const float* gamma = (const float*)d_in[12];
    const float* beta  = (const float*)d_in[13];
    float* out = (float*)d_out;

    float *Q, *K, *V, *S, *X, *H;
    cudaGetSymbolAddress((void**)&Q, g_Q);
    cudaGetSymbolAddress((void**)&K, g_K);
    cudaGetSymbolAddress((void**)&V, g_V);
    cudaGetSymbolAddress((void**)&S, g_S);
    cudaGetSymbolAddress((void**)&X, g_X);
    cudaGetSymbolAddress((void**)&H, g_H);

    dim3 blk(256);
    dim3 g_thin(DIM / 128, N_TOK / 128);     // 4 x 64
    dim3 g_fat (N_TOK / 128, N_TOK / 128);   // 64 x 64

    // Q/K/V projections
    gemm_tc<false, 0><<<g_thin, blk>>>(x, Wq, bq, nullptr, Q, N_TOK, DIM, DIM);
    gemm_tc<false, 0><<<g_thin, blk>>>(x, Wk, bk, nullptr, K, N_TOK, DIM, DIM);
    gemm_tc<false, 0><<<g_thin, blk>>>(x, Wv, bv, nullptr, V, N_TOK, DIM, DIM);
    // S = D .* (Q @ K^T)
    gemm_tc<true, 2><<<g_fat, blk>>>(Q, K, nullptr, D, S, N_TOK, N_TOK, DIM);
    // X = S @ V
    gemm_tc<false, 0><<<g_thin, blk>>>(S, V, nullptr, nullptr, X, N_TOK, DIM, N_TOK);
    // H = gelu(X @ Wf + bf)
    gemm_tc<false, 1><<<g_thin, blk>>>(X, Wf, bf, nullptr, H, N_TOK, DIM, DIM);
    // out_pre = H @ Wp + bp
    gemm_tc<false, 0><<<g_thin, blk>>>(H, Wp, bp, nullptr, out, N_TOK, DIM, DIM);
    // in-place group norm
    groupnorm_k<<<N_TOK, DIM>>>(out, gamma, beta);
}

// round 3
// speedup vs baseline: 3.6782x; 1.2105x over previous
#include <cuda_runtime.h>
#include <math.h>
#include <stdint.h>

#define N_TOK 8192
#define DIM   512
#define GN_EPS 1e-5f

// ---------------- scratch (static device arrays; runtime alloc is forbidden) ----------------
__device__ float g_Q [(size_t)N_TOK * DIM];
__device__ float g_K [(size_t)N_TOK * DIM];
__device__ float g_V [(size_t)N_TOK * DIM];
__device__ float g_Vt[(size_t)N_TOK * DIM];          // V transposed [DIM][N_TOK]
__device__ float g_S [(size_t)N_TOK * N_TOK];        // 256 MB retention matrix
__device__ float g_X [(size_t)N_TOK * DIM];
__device__ float g_H [(size_t)N_TOK * DIM];
__device__ float g_Wt[5 * (size_t)DIM * DIM];        // transposed weights

// ---------------- helpers ----------------
__device__ __forceinline__ uint32_t f2tf32(float f) {
    uint32_t r;
    asm("cvt.rna.tf32.f32 %0, %1;" : "=r"(r) : "f"(f));
    return r;
}
__device__ __forceinline__ uint32_t cvt_frag(uint32_t u) {
    return f2tf32(__uint_as_float(u));
}
__device__ __forceinline__ uint32_t smem_u32(const void* p) {
    return (uint32_t)__cvta_generic_to_shared(p);
}
__device__ __forceinline__ void ldmatrix_x4(uint32_t& r0, uint32_t& r1, uint32_t& r2, uint32_t& r3,
                                            uint32_t addr) {
    asm volatile("ldmatrix.sync.aligned.m8n8.x4.shared.b16 {%0,%1,%2,%3}, [%4];"
                 : "=r"(r0), "=r"(r1), "=r"(r2), "=r"(r3) : "r"(addr));
}
__device__ __forceinline__ void mma_tf32(float* c, const uint32_t* a, const uint32_t* b) {
    asm volatile("mma.sync.aligned.m16n8k8.row.col.f32.tf32.tf32.f32 "
                 "{%0,%1,%2,%3}, {%4,%5,%6,%7}, {%8,%9}, {%0,%1,%2,%3};"
                 : "+f"(c[0]), "+f"(c[1]), "+f"(c[2]), "+f"(c[3])
                 : "r"(a[0]), "r"(a[1]), "r"(a[2]), "r"(a[3]), "r"(b[0]), "r"(b[1]));
}
__device__ __forceinline__ void cpasync16(uint32_t dst, const void* src) {
    asm volatile("cp.async.cg.shared.global [%0], [%1], 16;" :: "r"(dst), "l"(src));
}
// swizzled float-index inside a [rows][32] tile: 8 16B-units per row, unit ^= (row&7)
__device__ __forceinline__ int sidx(int r, int unit) { return r * 32 + ((unit ^ (r & 7)) << 2); }

// ---------------- NT tf32 tensor-core GEMM, cp.async double-buffered ----------------
// C[M,Nn] = A[M,Kk] @ B^T   where B is [Nn][Kk] row-major
// EPI: 0 = +bias (may be null), 1 = gelu(c+bias), 2 = c * Dm[row,col]
template<int EPI>
__global__ __launch_bounds__(256)
void gemm_nt(const float* __restrict__ A, const float* __restrict__ B,
             const float* __restrict__ bias, const float* __restrict__ Dm,
             float* __restrict__ C, int M, int Nn, int Kk)
{
    constexpr int BM = 128, BN = 128, BK = 32;
    constexpr int STG = BM * BK;                  // floats per tile
    extern __shared__ float sm[];                 // [2 stages][A tile | B tile]

    const int t    = threadIdx.x;
    const int lane = t & 31;
    const int wid  = t >> 5;
    const int wm   = (wid & 3) * 32;              // 4 warps along M
    const int wn   = (wid >> 2) * 64;             // 2 warps along N
    const int br   = blockIdx.y;
    const int bc   = blockIdx.x;

    const int lr = t >> 3;                        // 0..31 (+32 per pass)
    const int lu = t & 7;                         // 16B unit in row

    float acc[2][8][4];
    #pragma unroll
    for (int i = 0; i < 2; i++)
        #pragma unroll
        for (int j = 0; j < 8; j++)
            #pragma unroll
            for (int q = 0; q < 4; q++) acc[i][j][q] = 0.f;

    auto load_stage = [&](int s, int k0) {
        float* Ab = sm + s * 2 * STG;
        float* Bb = Ab + STG;
        #pragma unroll
        for (int p = 0; p < 4; p++) {
            const int r = lr + p * 32;
            cpasync16(smem_u32(&Ab[sidx(r, lu)]),
                      A + (size_t)(br * BM + r) * Kk + k0 + lu * 4);
            cpasync16(smem_u32(&Bb[sidx(r, lu)]),
                      B + (size_t)(bc * BN + r) * Kk + k0 + lu * 4);
        }
        asm volatile("cp.async.commit_group;");
    };

    auto compute_stage = [&](int s) {
        float* Ab = sm + s * 2 * STG;
        float* Bb = Ab + STG;
        const int j  = lane >> 3;
        const int rr = lane & 7;
        #pragma unroll
        for (int ks = 0; ks < 4; ks++) {
            const int ub = ks * 2;
            uint32_t af[2][4];
            #pragma unroll
            for (int mf = 0; mf < 2; mf++) {
                const int row  = wm + mf * 16 + (j & 1) * 8 + rr;
                const int unit = ub + (j >> 1);
                ldmatrix_x4(af[mf][0], af[mf][1], af[mf][2], af[mf][3],
                            smem_u32(&Ab[sidx(row, unit)]));
                #pragma unroll
                for (int q = 0; q < 4; q++) af[mf][q] = cvt_frag(af[mf][q]);
            }
            uint32_t bf[8][2];
            #pragma unroll
            for (int nb = 0; nb < 4; nb++) {
                const int row  = wn + nb * 16 + (j >> 1) * 8 + rr;
                const int unit = ub + (j & 1);
                uint32_t r0, r1, r2, r3;
                ldmatrix_x4(r0, r1, r2, r3, smem_u32(&Bb[sidx(row, unit)]));
                bf[nb * 2 + 0][0] = cvt_frag(r0); bf[nb * 2 + 0][1] = cvt_frag(r1);
                bf[nb * 2 + 1][0] = cvt_frag(r2); bf[nb * 2 + 1][1] = cvt_frag(r3);
            }
            #pragma unroll
            for (int mf = 0; mf < 2; mf++)
                #pragma unroll
                for (int nf = 0; nf < 8; nf++)
                    mma_tf32(acc[mf][nf], af[mf], bf[nf]);
        }
    };

    const int nk = Kk / BK;
    load_stage(0, 0);
    for (int it = 0; it < nk; it++) {
        asm volatile("cp.async.wait_group 0;" ::: "memory");
        __syncthreads();
        if (it + 1 < nk) load_stage((it + 1) & 1, (it + 1) * BK);
        compute_stage(it & 1);
        __syncthreads();
    }

    // ---- epilogue ----
    const int g = lane >> 2, tg = lane & 3;
    #pragma unroll
    for (int mf = 0; mf < 2; mf++) {
        #pragma unroll
        for (int nf = 0; nf < 8; nf++) {
            const int col = bc * BN + wn + nf * 8 + tg * 2;
            #pragma unroll
            for (int h = 0; h < 2; h++) {
                const int row = br * BM + wm + mf * 16 + g + h * 8;
                float c0 = acc[mf][nf][h * 2 + 0];
                float c1 = acc[mf][nf][h * 2 + 1];
                if (EPI == 2) {
                    const float2 d = *(const float2*)(Dm + (size_t)row * Nn + col);
                    c0 *= d.x; c1 *= d.y;
                } else {
                    if (bias) { c0 += bias[col]; c1 += bias[col + 1]; }
                    if (EPI == 1) {
                        c0 = 0.5f * c0 * (1.f + erff(c0 * 0.70710678118654752f));
                        c1 = 0.5f * c1 * (1.f + erff(c1 * 0.70710678118654752f));
                    }
                }
                float2 o = { c0, c1 };
                *(float2*)(C + (size_t)row * Nn + col) = o;
            }
        }
    }
}

// ---------------- transpose: out[c][r] = in[r][c], in is [rows][cols] ----------------
__global__ void transpose_k(const float* __restrict__ in, float* __restrict__ out,
                            int rows, int cols)
{
    __shared__ float tile[32][33];
    int x = blockIdx.x * 32 + threadIdx.x;
    int y = blockIdx.y * 32 + threadIdx.y;
    #pragma unroll
    for (int i = 0; i < 32; i += 8)
        tile[threadIdx.y + i][threadIdx.x] = in[(size_t)(y + i) * cols + x];
    __syncthreads();
    x = blockIdx.y * 32 + threadIdx.x;
    y = blockIdx.x * 32 + threadIdx.y;
    #pragma unroll
    for (int i = 0; i < 32; i += 8)
        out[(size_t)(y + i) * rows + x] = tile[threadIdx.x][threadIdx.y + i];
}

// ---------------- GroupNorm (16 groups of 32 channels, one warp per group) ----------------
__global__ void groupnorm_k(float* __restrict__ io,
                            const float* __restrict__ gamma,
                            const float* __restrict__ beta)
{
    const int row = blockIdx.x;
    const int c   = threadIdx.x;
    float v  = io[(size_t)row * DIM + c];
    float s  = v;
    float s2 = v * v;
    #pragma unroll
    for (int off = 16; off > 0; off >>= 1) {
        s  += __shfl_xor_sync(0xffffffffu, s,  off);
        s2 += __shfl_xor_sync(0xffffffffu, s2, off);
    }
    const float mu  = s * (1.f / 32.f);
    const float var = s2 * (1.f / 32.f) - mu * mu;
    io[(size_t)row * DIM + c] = (v - mu) * rsqrtf(var + GN_EPS) * gamma[c] + beta[c];
}

// ---------------- launch ----------------
extern "C" void kernel_launch(void* const* d_in, const int* in_sizes, int n_in,
                              void* d_out, int out_size)
{
    const float* x     = (const float*)d_in[0];
    const float* D     = (const float*)d_in[1];
    const float* Wq    = (const float*)d_in[2];
    const float* bq    = (const float*)d_in[3];
    const float* Wk    = (const float*)d_in[4];
    const float* bk    = (const float*)d_in[5];
    const float* Wv    = (const float*)d_in[6];
    const float* bv    = (const float*)d_in[7];
    const float* Wf    = (const float*)d_in[8];
    const float* bf    = (const float*)d_in[9];
    const float* Wp    = (const float*)d_in[10];
    const float* bp    = (const float*)d_in[11];
    const float* gamma = (const float*)d_in[12];
    const float* beta  = (const float*)d_in[13];
    float* out = (float*)d_out;

    float *Q, *K, *V, *Vt, *S, *X, *H, *Wt;
    cudaGetSymbolAddress((void**)&Q,  g_Q);
    cudaGetSymbolAddress((void**)&K,  g_K);
    cudaGetSymbolAddress((void**)&V,  g_V);
    cudaGetSymbolAddress((void**)&Vt, g_Vt);
    cudaGetSymbolAddress((void**)&S,  g_S);
    cudaGetSymbolAddress((void**)&X,  g_X);
    cudaGetSymbolAddress((void**)&H,  g_H);
    cudaGetSymbolAddress((void**)&Wt, g_Wt);

    float* Wqt = Wt + 0 * (size_t)DIM * DIM;
    float* Wkt = Wt + 1 * (size_t)DIM * DIM;
    float* Wvt = Wt + 2 * (size_t)DIM * DIM;
    float* Wft = Wt + 3 * (size_t)DIM * DIM;
    float* Wpt = Wt + 4 * (size_t)DIM * DIM;

    const int SMEM = 2 * 2 * 128 * 32 * (int)sizeof(float);   // 64 KB
    cudaFuncSetAttribute(gemm_nt<0>, cudaFuncAttributeMaxDynamicSharedMemorySize, SMEM);
    cudaFuncSetAttribute(gemm_nt<1>, cudaFuncAttributeMaxDynamicSharedMemorySize, SMEM);
    cudaFuncSetAttribute(gemm_nt<2>, cudaFuncAttributeMaxDynamicSharedMemorySize, SMEM);

    dim3 blk(256);
    dim3 g_thin(DIM / 128, N_TOK / 128);     // 4 x 64
    dim3 g_fat (N_TOK / 128, N_TOK / 128);   // 64 x 64
    dim3 tblk(32, 8);
    dim3 tW(DIM / 32, DIM / 32);

    // transpose weights -> [out][in] NT form
    transpose_k<<<tW, tblk>>>(Wq, Wqt, DIM, DIM);
    transpose_k<<<tW, tblk>>>(Wk, Wkt, DIM, DIM);
    transpose_k<<<tW, tblk>>>(Wv, Wvt, DIM, DIM);
    transpose_k<<<tW, tblk>>>(Wf, Wft, DIM, DIM);
    transpose_k<<<tW, tblk>>>(Wp, Wpt, DIM, DIM);

    // projections (NT)
    gemm_nt<0><<<g_thin, blk, SMEM>>>(x, Wqt, bq, nullptr, Q, N_TOK, DIM, DIM);
    gemm_nt<0><<<g_thin, blk, SMEM>>>(x, Wkt, bk, nullptr, K, N_TOK, DIM, DIM);
    gemm_nt<0><<<g_thin, blk, SMEM>>>(x, Wvt, bv, nullptr, V, N_TOK, DIM, DIM);

    // V^T for the S@V GEMM
    transpose_k<<<dim3(DIM / 32, N_TOK / 32), tblk>>>(V, Vt, N_TOK, DIM);

    // S = D .* (Q @ K^T)
    gemm_nt<2><<<g_fat, blk, SMEM>>>(Q, K, nullptr, D, S, N_TOK, N_TOK, DIM);
    // X = S @ V  (= S @ Vt^T)
    gemm_nt<0><<<g_thin, blk, SMEM>>>(S, Vt, nullptr, nullptr, X, N_TOK, DIM, N_TOK);
    // H = gelu(X @ Wf + bf)
    gemm_nt<1><<<g_thin, blk, SMEM>>>(X, Wft, bf, nullptr, H, N_TOK, DIM, DIM);
    // out_pre = H @ Wp + bp
    gemm_nt<0><<<g_thin, blk, SMEM>>>(H, Wpt, bp, nullptr, out, N_TOK, DIM, DIM);
    // in-place group norm
    groupnorm_k<<<N_TOK, DIM>>>(out, gamma, beta);
}

// round 4
// speedup vs baseline: 4.0200x; 1.0929x over previous
#include <cuda_runtime.h>
#include <math.h>
#include <stdint.h>

#define N_TOK 8192
#define DIM   512
#define GN_EPS 1e-5f

// ---------------- scratch (static device arrays; runtime alloc is forbidden) ----------------
__device__ float g_Q [(size_t)N_TOK * DIM];
__device__ float g_K [(size_t)N_TOK * DIM];
__device__ float g_V [(size_t)N_TOK * DIM];
__device__ float g_Vt[(size_t)N_TOK * DIM];          // V transposed [DIM][N_TOK]
__device__ float g_S [(size_t)N_TOK * N_TOK];        // 256 MB retention matrix
__device__ float g_X [(size_t)N_TOK * DIM];
__device__ float g_H [(size_t)N_TOK * DIM];
__device__ float g_xr[(size_t)N_TOK * DIM];          // tf32-rounded x
__device__ float g_Wt[5 * (size_t)DIM * DIM];        // transposed + rounded weights

// ---------------- helpers ----------------
__device__ __forceinline__ uint32_t f2tf32(float f) {
    uint32_t r;
    asm("cvt.rna.tf32.f32 %0, %1;" : "=r"(r) : "f"(f));
    return r;
}
__device__ __forceinline__ float roundtf(float f) { return __uint_as_float(f2tf32(f)); }
__device__ __forceinline__ uint32_t smem_u32(const void* p) {
    return (uint32_t)__cvta_generic_to_shared(p);
}
__device__ __forceinline__ void ldmatrix_x4(uint32_t& r0, uint32_t& r1, uint32_t& r2, uint32_t& r3,
                                            uint32_t addr) {
    asm volatile("ldmatrix.sync.aligned.m8n8.x4.shared.b16 {%0,%1,%2,%3}, [%4];"
                 : "=r"(r0), "=r"(r1), "=r"(r2), "=r"(r3) : "r"(addr));
}
__device__ __forceinline__ void mma_tf32(float* c, const uint32_t* a, const uint32_t* b) {
    asm volatile("mma.sync.aligned.m16n8k8.row.col.f32.tf32.tf32.f32 "
                 "{%0,%1,%2,%3}, {%4,%5,%6,%7}, {%8,%9}, {%0,%1,%2,%3};"
                 : "+f"(c[0]), "+f"(c[1]), "+f"(c[2]), "+f"(c[3])
                 : "r"(a[0]), "r"(a[1]), "r"(a[2]), "r"(a[3]), "r"(b[0]), "r"(b[1]));
}
__device__ __forceinline__ void cpasync16(uint32_t dst, const void* src) {
    asm volatile("cp.async.cg.shared.global [%0], [%1], 16;" :: "r"(dst), "l"(src));
}
// swizzled float-index inside a [rows][32] tile: 8 16B-units per row, unit ^= (row&7)
__device__ __forceinline__ int sidx(int r, int unit) { return r * 32 + ((unit ^ (r & 7)) << 2); }

// ---------------- NT tf32 tensor-core GEMM ----------------
// C[M,Nn] = A[M,Kk] @ B^T, B is [Nn][Kk] row-major. Operands PRE-ROUNDED to tf32.
// Block 128x256, 8 warps (2 M x 4 N), warp tile 64x64, BK=32, 3-stage cp.async.
// EPI: 0 = +bias (may be null), 1 = gelu(c+bias), 2 = c * Dm[row,col]
// ROUND: round outputs to tf32 (outputs that feed later MMAs)
template<int EPI, bool ROUND>
__global__ __launch_bounds__(256, 1)
void gemm_nt(const float* __restrict__ A, const float* __restrict__ B,
             const float* __restrict__ bias, const float* __restrict__ Dm,
             float* __restrict__ C, int M, int Nn, int Kk)
{
    constexpr int BM = 128, BN = 256, BK = 32, STAGES = 3;
    constexpr int STG_A = BM * BK;                // 4096 floats
    constexpr int STG_B = BN * BK;                // 8192 floats
    constexpr int STG   = STG_A + STG_B;          // 48 KB per stage
    extern __shared__ float sm[];

    const int t    = threadIdx.x;
    const int lane = t & 31;
    const int wid  = t >> 5;
    const int wm   = (wid & 1) * 64;              // 2 warps along M
    const int wn   = (wid >> 1) * 64;             // 4 warps along N
    const int br   = blockIdx.y;
    const int bc   = blockIdx.x;

    const int lr = t >> 3;                        // 0..31 (+32 per pass)
    const int lu = t & 7;                         // 16B unit in row

    float acc[4][8][4];
    #pragma unroll
    for (int i = 0; i < 4; i++)
        #pragma unroll
        for (int j = 0; j < 8; j++)
            #pragma unroll
            for (int q = 0; q < 4; q++) acc[i][j][q] = 0.f;

    auto load_stage = [&](int s, int k0) {
        float* Ab = sm + s * STG;
        float* Bb = Ab + STG_A;
        #pragma unroll
        for (int p = 0; p < 4; p++) {
            const int r = lr + p * 32;
            cpasync16(smem_u32(&Ab[sidx(r, lu)]),
                      A + (size_t)(br * BM + r) * Kk + k0 + lu * 4);
        }
        #pragma unroll
        for (int p = 0; p < 8; p++) {
            const int r = lr + p * 32;
            cpasync16(smem_u32(&Bb[sidx(r, lu)]),
                      B + (size_t)(bc * BN + r) * Kk + k0 + lu * 4);
        }
        asm volatile("cp.async.commit_group;");
    };

    auto compute_stage = [&](int s) {
        float* Ab = sm + s * STG;
        float* Bb = Ab + STG_A;
        const int j  = lane >> 3;
        const int rr = lane & 7;
        #pragma unroll
        for (int ks = 0; ks < 4; ks++) {
            const int ub = ks * 2;
            uint32_t af[4][4];
            #pragma unroll
            for (int mf = 0; mf < 4; mf++) {
                const int row  = wm + mf * 16 + (j & 1) * 8 + rr;
                const int unit = ub + (j >> 1);
                ldmatrix_x4(af[mf][0], af[mf][1], af[mf][2], af[mf][3],
                            smem_u32(&Ab[sidx(row, unit)]));
            }
            uint32_t bf[8][2];
            #pragma unroll
            for (int nb = 0; nb < 4; nb++) {
                const int row  = wn + nb * 16 + (j >> 1) * 8 + rr;
                const int unit = ub + (j & 1);
                uint32_t r0, r1, r2, r3;
                ldmatrix_x4(r0, r1, r2, r3, smem_u32(&Bb[sidx(row, unit)]));
                bf[nb * 2 + 0][0] = r0; bf[nb * 2 + 0][1] = r1;
                bf[nb * 2 + 1][0] = r2; bf[nb * 2 + 1][1] = r3;
            }
            #pragma unroll
            for (int mf = 0; mf < 4; mf++)
                #pragma unroll
                for (int nf = 0; nf < 8; nf++)
                    mma_tf32(acc[mf][nf], af[mf], bf[nf]);
        }
    };

    const int nk = Kk / BK;
    load_stage(0, 0);
    load_stage(1, BK);
    for (int it = 0; it < nk; it++) {
        asm volatile("cp.async.wait_group 1;" ::: "memory");
        __syncthreads();
        if (it + 2 < nk) load_stage((it + 2) % STAGES, (it + 2) * BK);
        compute_stage(it % STAGES);
    }

    // ---- epilogue ----
    const int g = lane >> 2, tg = lane & 3;
    #pragma unroll
    for (int mf = 0; mf < 4; mf++) {
        #pragma unroll
        for (int nf = 0; nf < 8; nf++) {
            const int col = bc * BN + wn + nf * 8 + tg * 2;
            #pragma unroll
            for (int h = 0; h < 2; h++) {
                const int row = br * BM + wm + mf * 16 + g + h * 8;
                float c0 = acc[mf][nf][h * 2 + 0];
                float c1 = acc[mf][nf][h * 2 + 1];
                if (EPI == 2) {
                    const float2 d = *(const float2*)(Dm + (size_t)row * Nn + col);
                    c0 *= d.x; c1 *= d.y;
                } else {
                    if (bias) { c0 += bias[col]; c1 += bias[col + 1]; }
                    if (EPI == 1) {
                        c0 = 0.5f * c0 * (1.f + erff(c0 * 0.70710678118654752f));
                        c1 = 0.5f * c1 * (1.f + erff(c1 * 0.70710678118654752f));
                    }
                }
                if (ROUND) { c0 = roundtf(c0); c1 = roundtf(c1); }
                float2 o = { c0, c1 };
                *(float2*)(C + (size_t)row * Nn + col) = o;
            }
        }
    }
}

// ---------------- transpose (optionally tf32-rounding): out[c][r] = in[r][c] ----------------
template<bool ROUND>
__global__ void transpose_k(const float* __restrict__ in, float* __restrict__ out,
                            int rows, int cols)
{
    __shared__ float tile[32][33];
    int x = blockIdx.x * 32 + threadIdx.x;
    int y = blockIdx.y * 32 + threadIdx.y;
    #pragma unroll
    for (int i = 0; i < 32; i += 8) {
        float v = in[(size_t)(y + i) * cols + x];
        tile[threadIdx.y + i][threadIdx.x] = ROUND ? roundtf(v) : v;
    }
    __syncthreads();
    x = blockIdx.y * 32 + threadIdx.x;
    y = blockIdx.x * 32 + threadIdx.y;
    #pragma unroll
    for (int i = 0; i < 32; i += 8)
        out[(size_t)(y + i) * rows + x] = tile[threadIdx.x][threadIdx.y + i];
}

// ---------------- elementwise tf32 round ----------------
__global__ void round_k(const float* __restrict__ in, float* __restrict__ out, int n4)
{
    int i = blockIdx.x * blockDim.x + threadIdx.x;
    if (i < n4) {
        float4 v = ((const float4*)in)[i];
        v.x = roundtf(v.x); v.y = roundtf(v.y); v.z = roundtf(v.z); v.w = roundtf(v.w);
        ((float4*)out)[i] = v;
    }
}

// ---------------- GroupNorm (16 groups of 32 channels, one warp per group) ----------------
__global__ void groupnorm_k(float* __restrict__ io,
                            const float* __restrict__ gamma,
                            const float* __restrict__ beta)
{
    const int row = blockIdx.x;
    const int c   = threadIdx.x;
    float v  = io[(size_t)row * DIM + c];
    float s  = v;
    float s2 = v * v;
    #pragma unroll
    for (int off = 16; off > 0; off >>= 1) {
        s  += __shfl_xor_sync(0xffffffffu, s,  off);
        s2 += __shfl_xor_sync(0xffffffffu, s2, off);
    }
    const float mu  = s * (1.f / 32.f);
    const float var = s2 * (1.f / 32.f) - mu * mu;
    io[(size_t)row * DIM + c] = (v - mu) * rsqrtf(var + GN_EPS) * gamma[c] + beta[c];
}

// ---------------- launch ----------------
extern "C" void kernel_launch(void* const* d_in, const int* in_sizes, int n_in,
                              void* d_out, int out_size)
{
    const float* x     = (const float*)d_in[0];
    const float* D     = (const float*)d_in[1];
    const float* Wq    = (const float*)d_in[2];
    const float* bq    = (const float*)d_in[3];
    const float* Wk    = (const float*)d_in[4];
    const float* bk    = (const float*)d_in[5];
    const float* Wv    = (const float*)d_in[6];
    const float* bv    = (const float*)d_in[7];
    const float* Wf    = (const float*)d_in[8];
    const float* bf    = (const float*)d_in[9];
    const float* Wp    = (const float*)d_in[10];
    const float* bp    = (const float*)d_in[11];
    const float* gamma = (const float*)d_in[12];
    const float* beta  = (const float*)d_in[13];
    float* out = (float*)d_out;

    float *Q, *K, *V, *Vt, *S, *X, *H, *xr, *Wt;
    cudaGetSymbolAddress((void**)&Q,  g_Q);
    cudaGetSymbolAddress((void**)&K,  g_K);
    cudaGetSymbolAddress((void**)&V,  g_V);
    cudaGetSymbolAddress((void**)&Vt, g_Vt);
    cudaGetSymbolAddress((void**)&S,  g_S);
    cudaGetSymbolAddress((void**)&X,  g_X);
    cudaGetSymbolAddress((void**)&H,  g_H);
    cudaGetSymbolAddress((void**)&xr, g_xr);
    cudaGetSymbolAddress((void**)&Wt, g_Wt);

    float* Wqt = Wt + 0 * (size_t)DIM * DIM;
    float* Wkt = Wt + 1 * (size_t)DIM * DIM;
    float* Wvt = Wt + 2 * (size_t)DIM * DIM;
    float* Wft = Wt + 3 * (size_t)DIM * DIM;
    float* Wpt = Wt + 4 * (size_t)DIM * DIM;

    const int SMEM = 3 * (128 + 256) * 32 * (int)sizeof(float);   // 144 KB
    cudaFuncSetAttribute(gemm_nt<0, true>,  cudaFuncAttributeMaxDynamicSharedMemorySize, SMEM);
    cudaFuncSetAttribute(gemm_nt<0, false>, cudaFuncAttributeMaxDynamicSharedMemorySize, SMEM);
    cudaFuncSetAttribute(gemm_nt<1, true>,  cudaFuncAttributeMaxDynamicSharedMemorySize, SMEM);
    cudaFuncSetAttribute(gemm_nt<2, true>,  cudaFuncAttributeMaxDynamicSharedMemorySize, SMEM);

    dim3 blk(256);
    dim3 g_thin(DIM / 256, N_TOK / 128);     // 2 x 64
    dim3 g_fat (N_TOK / 256, N_TOK / 128);   // 32 x 64
    dim3 tblk(32, 8);
    dim3 tW(DIM / 32, DIM / 32);

    // prep: transpose+round weights, round x
    transpose_k<true><<<tW, tblk>>>(Wq, Wqt, DIM, DIM);
    transpose_k<true><<<tW, tblk>>>(Wk, Wkt, DIM, DIM);
    transpose_k<true><<<tW, tblk>>>(Wv, Wvt, DIM, DIM);
    transpose_k<true><<<tW, tblk>>>(Wf, Wft, DIM, DIM);
    transpose_k<true><<<tW, tblk>>>(Wp, Wpt, DIM, DIM);
    round_k<<<(N_TOK * DIM / 4 + 255) / 256, 256>>>(x, xr, N_TOK * DIM / 4);

    // projections (NT, rounded outputs)
    gemm_nt<0, true><<<g_thin, blk, SMEM>>>(xr, Wqt, bq, nullptr, Q, N_TOK, DIM, DIM);
    gemm_nt<0, true><<<g_thin, blk, SMEM>>>(xr, Wkt, bk, nullptr, K, N_TOK, DIM, DIM);
    gemm_nt<0, true><<<g_thin, blk, SMEM>>>(xr, Wvt, bv, nullptr, V, N_TOK, DIM, DIM);

    // V^T (already rounded at write)
    transpose_k<false><<<dim3(DIM / 32, N_TOK / 32), tblk>>>(V, Vt, N_TOK, DIM);

    // S = tf32( D .* (Q @ K^T) )
    gemm_nt<2, true><<<g_fat, blk, SMEM>>>(Q, K, nullptr, D, S, N_TOK, N_TOK, DIM);
    // X = tf32( S @ V )
    gemm_nt<0, true><<<g_thin, blk, SMEM>>>(S, Vt, nullptr, nullptr, X, N_TOK, DIM, N_TOK);
    // H = tf32( gelu(X @ Wf + bf) )
    gemm_nt<1, true><<<g_thin, blk, SMEM>>>(X, Wft, bf, nullptr, H, N_TOK, DIM, DIM);
    // out_pre = H @ Wp + bp   (full fp32 out)
    gemm_nt<0, false><<<g_thin, blk, SMEM>>>(H, Wpt, bp, nullptr, out, N_TOK, DIM, DIM);
    // in-place group norm
    groupnorm_k<<<N_TOK, DIM>>>(out, gamma, beta);
}

// round 6
// speedup vs baseline: 7.1374x; 1.7755x over previous
#include <cuda_runtime.h>
#include <cuda_fp16.h>
#include <math.h>
#include <stdint.h>

#define N_TOK 8192
#define DIM   512
#define GN_EPS 1e-5f

// ---------------- scratch (static device arrays; runtime alloc is forbidden) ----------------
__device__ __half g_Q [(size_t)N_TOK * DIM];
__device__ __half g_K [(size_t)N_TOK * DIM];
__device__ __half g_V [(size_t)N_TOK * DIM];
__device__ __half g_Vt[(size_t)N_TOK * DIM];         // V transposed [DIM][N_TOK]
__device__ __half g_S [(size_t)N_TOK * N_TOK];       // 128 MB retention matrix (fp16)
__device__ __half g_X [(size_t)N_TOK * DIM];
__device__ __half g_H [(size_t)N_TOK * DIM];
__device__ __half g_xh[(size_t)N_TOK * DIM];         // fp16 x
__device__ __half g_Wt[5 * (size_t)DIM * DIM];       // transposed fp16 weights

// ---------------- helpers ----------------
__device__ __forceinline__ uint32_t smem_u32(const void* p) {
    return (uint32_t)__cvta_generic_to_shared(p);
}
__device__ __forceinline__ void cpasync16(uint32_t dst, const void* src) {
    asm volatile("cp.async.cg.shared.global [%0], [%1], 16;" :: "r"(dst), "l"(src));
}
__device__ __forceinline__ void ldmatrix_x4(uint32_t& r0, uint32_t& r1, uint32_t& r2, uint32_t& r3,
                                            uint32_t addr) {
    asm volatile("ldmatrix.sync.aligned.m8n8.x4.shared.b16 {%0,%1,%2,%3}, [%4];"
                 : "=r"(r0), "=r"(r1), "=r"(r2), "=r"(r3) : "r"(addr));
}
__device__ __forceinline__ void mma_f16(float* c, const uint32_t* a, const uint32_t* b) {
    asm volatile("mma.sync.aligned.m16n8k16.row.col.f32.f16.f16.f32 "
                 "{%0,%1,%2,%3}, {%4,%5,%6,%7}, {%8,%9}, {%0,%1,%2,%3};"
                 : "+f"(c[0]), "+f"(c[1]), "+f"(c[2]), "+f"(c[3])
                 : "r"(a[0]), "r"(a[1]), "r"(a[2]), "r"(a[3]), "r"(b[0]), "r"(b[1]));
}

// ---------------- fp16 NT tensor-core GEMM ----------------
// C[M,Nn] = A[M,Kk] @ B^T, A/B are __half [.][Kk] row-major, fp32 accumulate.
// Block 128x256, 8 warps (2 M x 4 N), warp tile 64x64, BK=64 (128B rows, SW128 swizzle),
// 3-stage cp.async pipeline.
// EPI: 0 = +bias (may be null), 1 = gelu(c+bias), 2 = c * Dm[row,col]
// OutT: __half (intermediates) or float (final output)
template<int EPI, typename OutT>
__global__ __launch_bounds__(256, 1)
void gemm_h(const __half* __restrict__ A, const __half* __restrict__ B,
            const float* __restrict__ bias, const float* __restrict__ Dm,
            OutT* __restrict__ C, int M, int Nn, int Kk)
{
    constexpr int BM = 128, BN = 256, BK = 64, STAGES = 3;
    constexpr int A_BYTES = BM * BK * 2;          // 16384
    constexpr int B_BYTES = BN * BK * 2;          // 32768
    constexpr int STG_BYTES = A_BYTES + B_BYTES;  // 49152
    extern __shared__ char smem[];
    const uint32_t sbase = smem_u32(smem);

    const int t    = threadIdx.x;
    const int lane = t & 31;
    const int wid  = t >> 5;
    const int wm   = (wid & 1) * 64;              // 2 warps along M
    const int wn   = (wid >> 1) * 64;             // 4 warps along N
    const int br   = blockIdx.y;
    const int bc   = blockIdx.x;

    const int lr = t >> 3;                        // 0..31 (+32 per pass)
    const int lu = t & 7;                         // 16B unit in 128B row

    float acc[4][8][4];
    #pragma unroll
    for (int i = 0; i < 4; i++)
        #pragma unroll
        for (int j = 0; j < 8; j++)
            #pragma unroll
            for (int q = 0; q < 4; q++) acc[i][j][q] = 0.f;

    auto load_stage = [&](int it) {
        const uint32_t ab = sbase + (it % STAGES) * STG_BYTES;
        const uint32_t bb = ab + A_BYTES;
        const __half* Ag = A + (size_t)(br * BM) * Kk + it * BK;
        const __half* Bg = B + (size_t)(bc * BN) * Kk + it * BK;
        #pragma unroll
        for (int p = 0; p < 4; p++) {
            const int r = lr + p * 32;
            cpasync16(ab + r * 128 + ((lu ^ (r & 7)) << 4), Ag + (size_t)r * Kk + lu * 8);
        }
        #pragma unroll
        for (int p = 0; p < 8; p++) {
            const int r = lr + p * 32;
            cpasync16(bb + r * 128 + ((lu ^ (r & 7)) << 4), Bg + (size_t)r * Kk + lu * 8);
        }
        asm volatile("cp.async.commit_group;" ::: "memory");
    };

    auto compute_stage = [&](int it) {
        const uint32_t ab = sbase + (it % STAGES) * STG_BYTES;
        const uint32_t bb = ab + A_BYTES;
        const int j  = lane >> 3;                 // 0..3
        const int rr = lane & 7;
        #pragma unroll
        for (int ks = 0; ks < 4; ks++) {          // 4 x k16 steps = BK=64
            const int ub = ks * 2;                // base 16B-unit
            uint32_t af[4][4];
            #pragma unroll
            for (int mf = 0; mf < 4; mf++) {
                const int row  = wm + mf * 16 + (j & 1) * 8 + rr;
                const int unit = ub + (j >> 1);
                ldmatrix_x4(af[mf][0], af[mf][1], af[mf][2], af[mf][3],
                            ab + row * 128 + ((unit ^ (row & 7)) << 4));
            }
            uint32_t bf[8][2];
            #pragma unroll
            for (int nb = 0; nb < 4; nb++) {
                const int row  = wn + nb * 16 + (j >> 1) * 8 + rr;
                const int unit = ub + (j & 1);
                uint32_t r0, r1, r2, r3;
                ldmatrix_x4(r0, r1, r2, r3, bb + row * 128 + ((unit ^ (row & 7)) << 4));
                bf[nb * 2 + 0][0] = r0; bf[nb * 2 + 0][1] = r1;
                bf[nb * 2 + 1][0] = r2; bf[nb * 2 + 1][1] = r3;
            }
            #pragma unroll
            for (int mf = 0; mf < 4; mf++)
                #pragma unroll
                for (int nf = 0; nf < 8; nf++)
                    mma_f16(acc[mf][nf], af[mf], bf[nf]);
        }
    };

    const int nk = Kk / BK;
    load_stage(0);
    load_stage(1);
    for (int it = 0; it < nk; it++) {
        if (it + 1 < nk) asm volatile("cp.async.wait_group 1;" ::: "memory");
        else             asm volatile("cp.async.wait_group 0;" ::: "memory");
        __syncthreads();
        if (it + 2 < nk) load_stage(it + 2);
        compute_stage(it);
    }

    // ---- epilogue ----
    const int g = lane >> 2, tg = lane & 3;
    #pragma unroll
    for (int mf = 0; mf < 4; mf++) {
        #pragma unroll
        for (int nf = 0; nf < 8; nf++) {
            const int col = bc * BN + wn + nf * 8 + tg * 2;
            #pragma unroll
            for (int h = 0; h < 2; h++) {
                const int row = br * BM + wm + mf * 16 + g + h * 8;
                float c0 = acc[mf][nf][h * 2 + 0];
                float c1 = acc[mf][nf][h * 2 + 1];
                if (EPI == 2) {
                    const float2 d = *(const float2*)(Dm + (size_t)row * Nn + col);
                    c0 *= d.x; c1 *= d.y;
                } else {
                    if (bias) { c0 += bias[col]; c1 += bias[col + 1]; }
                    if (EPI == 1) {
                        c0 = 0.5f * c0 * (1.f + erff(c0 * 0.70710678118654752f));
                        c1 = 0.5f * c1 * (1.f + erff(c1 * 0.70710678118654752f));
                    }
                }
                OutT* Cp = C + (size_t)row * Nn + col;
                if (sizeof(OutT) == 2) {
                    __half2 o = __floats2half2_rn(c0, c1);
                    *(__half2*)Cp = o;
                } else {
                    float2 o = { c0, c1 };
                    *(float2*)Cp = o;
                }
            }
        }
    }
}

// ---------------- transpose with type convert: out[c][r] = conv(in[r][c]) ----------------
template<typename InT, typename OutT>
__global__ void transpose_k(const InT* __restrict__ in, OutT* __restrict__ out,
                            int rows, int cols)
{
    __shared__ OutT tile[32][33];
    int x = blockIdx.x * 32 + threadIdx.x;
    int y = blockIdx.y * 32 + threadIdx.y;
    #pragma unroll
    for (int i = 0; i < 32; i += 8)
        tile[threadIdx.y + i][threadIdx.x] = (OutT)(float)in[(size_t)(y + i) * cols + x];
    __syncthreads();
    x = blockIdx.y * 32 + threadIdx.x;
    y = blockIdx.x * 32 + threadIdx.y;
    #pragma unroll
    for (int i = 0; i < 32; i += 8)
        out[(size_t)(y + i) * rows + x] = tile[threadIdx.x][threadIdx.y + i];
}

// ---------------- fp32 -> fp16 convert ----------------
__global__ void conv_k(const float* __restrict__ in, __half* __restrict__ out, int n4)
{
    int i = blockIdx.x * blockDim.x + threadIdx.x;
    if (i < n4) {
        float4 v = ((const float4*)in)[i];
        __half2 a = __floats2half2_rn(v.x, v.y);
        __half2 b = __floats2half2_rn(v.z, v.w);
        uint2 o = { *(uint32_t*)&a, *(uint32_t*)&b };
        ((uint2*)out)[i] = o;
    }
}

// ---------------- GroupNorm (16 groups of 32 channels, one warp per group) ----------------
__global__ void groupnorm_k(float* __restrict__ io,
                            const float* __restrict__ gamma,
                            const float* __restrict__ beta)
{
    const int row = blockIdx.x;
    const int c   = threadIdx.x;
    float v  = io[(size_t)row * DIM + c];
    float s  = v;
    float s2 = v * v;
    #pragma unroll
    for (int off = 16; off > 0; off >>= 1) {
        s  += __shfl_xor_sync(0xffffffffu, s,  off);
        s2 += __shfl_xor_sync(0xffffffffu, s2, off);
    }
    const float mu  = s * (1.f / 32.f);
    const float var = s2 * (1.f / 32.f) - mu * mu;
    io[(size_t)row * DIM + c] = (v - mu) * rsqrtf(var + GN_EPS) * gamma[c] + beta[c];
}

// ---------------- launch ----------------
extern "C" void kernel_launch(void* const* d_in, const int* in_sizes, int n_in,
                              void* d_out, int out_size)
{
    const float* x     = (const float*)d_in[0];
    const float* D     = (const float*)d_in[1];
    const float* Wq    = (const float*)d_in[2];
    const float* bq    = (const float*)d_in[3];
    const float* Wk    = (const float*)d_in[4];
    const float* bk    = (const float*)d_in[5];
    const float* Wv    = (const float*)d_in[6];
    const float* bv    = (const float*)d_in[7];
    const float* Wf    = (const float*)d_in[8];
    const float* bf    = (const float*)d_in[9];
    const float* Wp    = (const float*)d_in[10];
    const float* bp    = (const float*)d_in[11];
    const float* gamma = (const float*)d_in[12];
    const float* beta  = (const float*)d_in[13];
    float* out = (float*)d_out;

    __half *Q, *K, *V, *Vt, *S, *X, *H, *xh, *Wt;
    cudaGetSymbolAddress((void**)&Q,  g_Q);
    cudaGetSymbolAddress((void**)&K,  g_K);
    cudaGetSymbolAddress((void**)&V,  g_V);
    cudaGetSymbolAddress((void**)&Vt, g_Vt);
    cudaGetSymbolAddress((void**)&S,  g_S);
    cudaGetSymbolAddress((void**)&X,  g_X);
    cudaGetSymbolAddress((void**)&H,  g_H);
    cudaGetSymbolAddress((void**)&xh, g_xh);
    cudaGetSymbolAddress((void**)&Wt, g_Wt);

    __half* Wqt = Wt + 0 * (size_t)DIM * DIM;
    __half* Wkt = Wt + 1 * (size_t)DIM * DIM;
    __half* Wvt = Wt + 2 * (size_t)DIM * DIM;
    __half* Wft = Wt + 3 * (size_t)DIM * DIM;
    __half* Wpt = Wt + 4 * (size_t)DIM * DIM;

    const int SMEM = 3 * (128 + 256) * 64 * 2;   // 147456 B
    cudaFuncSetAttribute(gemm_h<0, __half>, cudaFuncAttributeMaxDynamicSharedMemorySize, SMEM);
    cudaFuncSetAttribute(gemm_h<1, __half>, cudaFuncAttributeMaxDynamicSharedMemorySize, SMEM);
    cudaFuncSetAttribute(gemm_h<2, __half>, cudaFuncAttributeMaxDynamicSharedMemorySize, SMEM);
    cudaFuncSetAttribute(gemm_h<0, float>,  cudaFuncAttributeMaxDynamicSharedMemorySize, SMEM);

    dim3 blk(256);
    dim3 g_thin(DIM / 256, N_TOK / 128);     // 2 x 64
    dim3 g_fat (N_TOK / 256, N_TOK / 128);   // 32 x 64
    dim3 tblk(32, 8);
    dim3 tW(DIM / 32, DIM / 32);

    // prep: transpose weights fp32->fp16, convert x to fp16
    transpose_k<float, __half><<<tW, tblk>>>(Wq, Wqt, DIM, DIM);
    transpose_k<float, __half><<<tW, tblk>>>(Wk, Wkt, DIM, DIM);
    transpose_k<float, __half><<<tW, tblk>>>(Wv, Wvt, DIM, DIM);
    transpose_k<float, __half><<<tW, tblk>>>(Wf, Wft, DIM, DIM);
    transpose_k<float, __half><<<tW, tblk>>>(Wp, Wpt, DIM, DIM);
    conv_k<<<(N_TOK * DIM / 4 + 255) / 256, 256>>>(x, xh, N_TOK * DIM / 4);

    // projections (NT)
    gemm_h<0, __half><<<g_thin, blk, SMEM>>>(xh, Wqt, bq, nullptr, Q, N_TOK, DIM, DIM);
    gemm_h<0, __half><<<g_thin, blk, SMEM>>>(xh, Wkt, bk, nullptr, K, N_TOK, DIM, DIM);
    gemm_h<0, __half><<<g_thin, blk, SMEM>>>(xh, Wvt, bv, nullptr, V, N_TOK, DIM, DIM);

    // V^T for S@V
    transpose_k<__half, __half><<<dim3(DIM / 32, N_TOK / 32), tblk>>>(V, Vt, N_TOK, DIM);

    // S = fp16( D .* (Q @ K^T) )
    gemm_h<2, __half><<<g_fat, blk, SMEM>>>(Q, K, nullptr, D, S, N_TOK, N_TOK, DIM);
    // X = fp16( S @ V )
    gemm_h<0, __half><<<g_thin, blk, SMEM>>>(S, Vt, nullptr, nullptr, X, N_TOK, DIM, N_TOK);
    // H = fp16( gelu(X @ Wf + bf) )
    gemm_h<1, __half><<<g_thin, blk, SMEM>>>(X, Wft, bf, nullptr, H, N_TOK, DIM, DIM);
    // out_pre = H @ Wp + bp  (fp32 out)
    gemm_h<0, float><<<g_thin, blk, SMEM>>>(H, Wpt, bp, nullptr, out, N_TOK, DIM, DIM);
    // in-place group norm
    groupnorm_k<<<N_TOK, DIM>>>(out, gamma, beta);
}

// round 7
// speedup vs baseline: 7.4617x; 1.0454x over previous
#include <cuda_runtime.h>
#include <cuda_fp16.h>
#include <math.h>
#include <stdint.h>

#define N_TOK 8192
#define DIM   512
#define GN_EPS 1e-5f

// ---------------- scratch (static device arrays; runtime alloc is forbidden) ----------------
__device__ __half g_Q [(size_t)N_TOK * DIM];
__device__ __half g_K [(size_t)N_TOK * DIM];
__device__ __half g_Vt[(size_t)N_TOK * DIM];         // V transposed [DIM][N_TOK]
__device__ __half g_S [(size_t)N_TOK * N_TOK];       // 128 MB retention matrix (fp16)
__device__ __half g_X [(size_t)N_TOK * DIM];
__device__ __half g_H [(size_t)N_TOK * DIM];
__device__ __half g_xh[(size_t)N_TOK * DIM];         // fp16 x
__device__ __half g_Wt[5 * (size_t)DIM * DIM];       // transposed fp16 weights

// ---------------- helpers ----------------
__device__ __forceinline__ uint32_t smem_u32(const void* p) {
    return (uint32_t)__cvta_generic_to_shared(p);
}
__device__ __forceinline__ void cpasync16(uint32_t dst, const void* src) {
    asm volatile("cp.async.cg.shared.global [%0], [%1], 16;" :: "r"(dst), "l"(src));
}
__device__ __forceinline__ void ldmatrix_x4(uint32_t& r0, uint32_t& r1, uint32_t& r2, uint32_t& r3,
                                            uint32_t addr) {
    asm volatile("ldmatrix.sync.aligned.m8n8.x4.shared.b16 {%0,%1,%2,%3}, [%4];"
                 : "=r"(r0), "=r"(r1), "=r"(r2), "=r"(r3) : "r"(addr));
}
__device__ __forceinline__ void mma_f16(float* c, const uint32_t* a, const uint32_t* b) {
    asm volatile("mma.sync.aligned.m16n8k16.row.col.f32.f16.f16.f32 "
                 "{%0,%1,%2,%3}, {%4,%5,%6,%7}, {%8,%9}, {%0,%1,%2,%3};"
                 : "+f"(c[0]), "+f"(c[1]), "+f"(c[2]), "+f"(c[3])
                 : "r"(a[0]), "r"(a[1]), "r"(a[2]), "r"(a[3]), "r"(b[0]), "r"(b[1]));
}

// ---------------- fp16 NT tensor-core GEMM ----------------
// C[M,Nn] = A[M,Kk] @ B^T, A/B are __half [.][Kk] row-major, fp32 accumulate.
// Block 128x256, 8 warps (2 M x 4 N), warp tile 64x64, BK=64 (128B rows, SW128 swizzle),
// 3-stage cp.async pipeline.
// EPI: 0 = +bias[col] (may be null), 1 = gelu(c+bias[col]), 2 = c * Dm[row,col],
//      3 = +bias[row], 4 = bias[col] then fused GroupNorm (gamma/beta), fp32 out
template<int EPI, typename OutT>
__global__ __launch_bounds__(256, 1)
void gemm_h(const __half* __restrict__ A, const __half* __restrict__ B,
            const float* __restrict__ bias, const float* __restrict__ Dm,
            const float* __restrict__ gm, const float* __restrict__ bt,
            OutT* __restrict__ C, int M, int Nn, int Kk)
{
    constexpr int BM = 128, BN = 256, BK = 64, STAGES = 3;
    constexpr int A_BYTES = BM * BK * 2;          // 16384
    constexpr int B_BYTES = BN * BK * 2;          // 32768
    constexpr int STG_BYTES = A_BYTES + B_BYTES;  // 49152
    extern __shared__ char smem[];
    const uint32_t sbase = smem_u32(smem);

    const int t    = threadIdx.x;
    const int lane = t & 31;
    const int wid  = t >> 5;
    const int wm   = (wid & 1) * 64;              // 2 warps along M
    const int wn   = (wid >> 1) * 64;             // 4 warps along N
    const int br   = blockIdx.y;
    const int bc   = blockIdx.x;

    const int lr = t >> 3;                        // 0..31 (+32 per pass)
    const int lu = t & 7;                         // 16B unit in 128B row

    float acc[4][8][4];
    #pragma unroll
    for (int i = 0; i < 4; i++)
        #pragma unroll
        for (int j = 0; j < 8; j++)
            #pragma unroll
            for (int q = 0; q < 4; q++) acc[i][j][q] = 0.f;

    auto load_stage = [&](int it) {
        const uint32_t ab = sbase + (it % STAGES) * STG_BYTES;
        const uint32_t bb = ab + A_BYTES;
        const __half* Ag = A + (size_t)(br * BM) * Kk + it * BK;
        const __half* Bg = B + (size_t)(bc * BN) * Kk + it * BK;
        #pragma unroll
        for (int p = 0; p < 4; p++) {
            const int r = lr + p * 32;
            cpasync16(ab + r * 128 + ((lu ^ (r & 7)) << 4), Ag + (size_t)r * Kk + lu * 8);
        }
        #pragma unroll
        for (int p = 0; p < 8; p++) {
            const int r = lr + p * 32;
            cpasync16(bb + r * 128 + ((lu ^ (r & 7)) << 4), Bg + (size_t)r * Kk + lu * 8);
        }
        asm volatile("cp.async.commit_group;" ::: "memory");
    };

    auto compute_stage = [&](int it) {
        const uint32_t ab = sbase + (it % STAGES) * STG_BYTES;
        const uint32_t bb = ab + A_BYTES;
        const int j  = lane >> 3;                 // 0..3
        const int rr = lane & 7;
        #pragma unroll
        for (int ks = 0; ks < 4; ks++) {          // 4 x k16 steps = BK=64
            const int ub = ks * 2;                // base 16B-unit
            uint32_t af[4][4];
            #pragma unroll
            for (int mf = 0; mf < 4; mf++) {
                const int row  = wm + mf * 16 + (j & 1) * 8 + rr;
                const int unit = ub + (j >> 1);
                ldmatrix_x4(af[mf][0], af[mf][1], af[mf][2], af[mf][3],
                            ab + row * 128 + ((unit ^ (row & 7)) << 4));
            }
            uint32_t bf[8][2];
            #pragma unroll
            for (int nb = 0; nb < 4; nb++) {
                const int row  = wn + nb * 16 + (j >> 1) * 8 + rr;
                const int unit = ub + (j & 1);
                uint32_t r0, r1, r2, r3;
                ldmatrix_x4(r0, r1, r2, r3, bb + row * 128 + ((unit ^ (row & 7)) << 4));
                bf[nb * 2 + 0][0] = r0; bf[nb * 2 + 0][1] = r1;
                bf[nb * 2 + 1][0] = r2; bf[nb * 2 + 1][1] = r3;
            }
            #pragma unroll
            for (int mf = 0; mf < 4; mf++)
                #pragma unroll
                for (int nf = 0; nf < 8; nf++)
                    mma_f16(acc[mf][nf], af[mf], bf[nf]);
        }
    };

    const int nk = Kk / BK;
    load_stage(0);
    load_stage(1);
    for (int it = 0; it < nk; it++) {
        if (it + 1 < nk) asm volatile("cp.async.wait_group 1;" ::: "memory");
        else             asm volatile("cp.async.wait_group 0;" ::: "memory");
        __syncthreads();
        if (it + 2 < nk) load_stage(it + 2);
        compute_stage(it);
    }

    // ---- epilogue ----
    const int g = lane >> 2, tg = lane & 3;

    if (EPI == 4) {
        // bias[col] + fused GroupNorm (groups of 32 channels; each group's 32 values
        // for a given row live in the 4 lanes sharing g, tg=0..3 -> shfl quad-reduce)
        #pragma unroll
        for (int mf = 0; mf < 4; mf++) {
            #pragma unroll
            for (int h = 0; h < 2; h++) {
                const int row = br * BM + wm + mf * 16 + g + h * 8;
                float v[16];
                #pragma unroll
                for (int nf = 0; nf < 8; nf++) {
                    const int col = bc * BN + wn + nf * 8 + tg * 2;
                    v[nf * 2 + 0] = acc[mf][nf][h * 2 + 0] + bias[col];
                    v[nf * 2 + 1] = acc[mf][nf][h * 2 + 1] + bias[col + 1];
                }
                #pragma unroll
                for (int grp = 0; grp < 2; grp++) {
                    float s = 0.f, s2 = 0.f;
                    #pragma unroll
                    for (int q = 0; q < 8; q++) {
                        const float z = v[grp * 8 + q];
                        s += z; s2 += z * z;
                    }
                    s  += __shfl_xor_sync(0xffffffffu, s, 1);
                    s  += __shfl_xor_sync(0xffffffffu, s, 2);
                    s2 += __shfl_xor_sync(0xffffffffu, s2, 1);
                    s2 += __shfl_xor_sync(0xffffffffu, s2, 2);
                    const float mu  = s * (1.f / 32.f);
                    const float var = s2 * (1.f / 32.f) - mu * mu;
                    const float inv = rsqrtf(var + GN_EPS);
                    #pragma unroll
                    for (int q = 0; q < 4; q++) {
                        const int nf  = grp * 4 + q;
                        const int col = bc * BN + wn + nf * 8 + tg * 2;
                        float c0 = (v[nf * 2 + 0] - mu) * inv * gm[col]     + bt[col];
                        float c1 = (v[nf * 2 + 1] - mu) * inv * gm[col + 1] + bt[col + 1];
                        float2 o = { c0, c1 };
                        *(float2*)((float*)C + (size_t)row * Nn + col) = o;
                    }
                }
            }
        }
        return;
    }

    #pragma unroll
    for (int mf = 0; mf < 4; mf++) {
        #pragma unroll
        for (int nf = 0; nf < 8; nf++) {
            const int col = bc * BN + wn + nf * 8 + tg * 2;
            #pragma unroll
            for (int h = 0; h < 2; h++) {
                const int row = br * BM + wm + mf * 16 + g + h * 8;
                float c0 = acc[mf][nf][h * 2 + 0];
                float c1 = acc[mf][nf][h * 2 + 1];
                if (EPI == 2) {
                    const float2 d = *(const float2*)(Dm + (size_t)row * Nn + col);
                    c0 *= d.x; c1 *= d.y;
                } else if (EPI == 3) {
                    const float b = bias[row];
                    c0 += b; c1 += b;
                } else {
                    if (bias) { c0 += bias[col]; c1 += bias[col + 1]; }
                    if (EPI == 1) {
                        c0 = 0.5f * c0 * (1.f + erff(c0 * 0.70710678118654752f));
                        c1 = 0.5f * c1 * (1.f + erff(c1 * 0.70710678118654752f));
                    }
                }
                OutT* Cp = C + (size_t)row * Nn + col;
                if (sizeof(OutT) == 2) {
                    __half2 o = __floats2half2_rn(c0, c1);
                    *(__half2*)Cp = o;
                } else {
                    float2 o = { c0, c1 };
                    *(float2*)Cp = o;
                }
            }
        }
    }
}

// ---------------- fused prep: 5 weight transposes (fp32->fp16) + x fp32->fp16 ----------------
// blocks [0, 1280): weight transposes (256 blocks per weight, 32x32 tiles)
// blocks [1280, 5376): x conversion (float4 -> half2x2)
__global__ void prep_k(const float* __restrict__ Wq, const float* __restrict__ Wk,
                       const float* __restrict__ Wv, const float* __restrict__ Wf,
                       const float* __restrict__ Wp, const float* __restrict__ x,
                       __half* __restrict__ Wt, __half* __restrict__ xh)
{
    const int b = blockIdx.x;
    const int t = threadIdx.x;
    if (b < 1280) {
        __shared__ float tile[32][33];
        const int w  = b >> 8;                   // weight index 0..4
        const int ti = b & 255;
        const int bx = ti & 15, by = ti >> 4;
        const float* in = (w == 0) ? Wq : (w == 1) ? Wk : (w == 2) ? Wv : (w == 3) ? Wf : Wp;
        __half* out = Wt + (size_t)w * DIM * DIM;
        const int tx = t & 31, tyb = t >> 5;     // 32 x 8
        int x0 = bx * 32 + tx;
        #pragma unroll
        for (int i = 0; i < 32; i += 8)
            tile[tyb + i][tx] = in[(size_t)(by * 32 + tyb + i) * DIM + x0];
        __syncthreads();
        int x1 = by * 32 + tx;
        #pragma unroll
        for (int i = 0; i < 32; i += 8)
            out[(size_t)(bx * 32 + tyb + i) * DIM + x1] = __float2half_rn(tile[tx][tyb + i]);
    } else {
        const int i = (b - 1280) * 256 + t;      // < 1048576
        float4 v = ((const float4*)x)[i];
        __half2 a = __floats2half2_rn(v.x, v.y);
        __half2 c = __floats2half2_rn(v.z, v.w);
        uint2 o = { *(uint32_t*)&a, *(uint32_t*)&c };
        ((uint2*)xh)[i] = o;
    }
}

// ---------------- launch ----------------
extern "C" void kernel_launch(void* const* d_in, const int* in_sizes, int n_in,
                              void* d_out, int out_size)
{
    const float* x     = (const float*)d_in[0];
    const float* D     = (const float*)d_in[1];
    const float* Wq    = (const float*)d_in[2];
    const float* bq    = (const float*)d_in[3];
    const float* Wk    = (const float*)d_in[4];
    const float* bk    = (const float*)d_in[5];
    const float* Wv    = (const float*)d_in[6];
    const float* bv    = (const float*)d_in[7];
    const float* Wf    = (const float*)d_in[8];
    const float* bf    = (const float*)d_in[9];
    const float* Wp    = (const float*)d_in[10];
    const float* bp    = (const float*)d_in[11];
    const float* gamma = (const float*)d_in[12];
    const float* beta  = (const float*)d_in[13];
    float* out = (float*)d_out;

    __half *Q, *K, *Vt, *S, *X, *H, *xh, *Wt;
    cudaGetSymbolAddress((void**)&Q,  g_Q);
    cudaGetSymbolAddress((void**)&K,  g_K);
    cudaGetSymbolAddress((void**)&Vt, g_Vt);
    cudaGetSymbolAddress((void**)&S,  g_S);
    cudaGetSymbolAddress((void**)&X,  g_X);
    cudaGetSymbolAddress((void**)&H,  g_H);
    cudaGetSymbolAddress((void**)&xh, g_xh);
    cudaGetSymbolAddress((void**)&Wt, g_Wt);

    __half* Wqt = Wt + 0 * (size_t)DIM * DIM;
    __half* Wkt = Wt + 1 * (size_t)DIM * DIM;
    __half* Wvt = Wt + 2 * (size_t)DIM * DIM;
    __half* Wft = Wt + 3 * (size_t)DIM * DIM;
    __half* Wpt = Wt + 4 * (size_t)DIM * DIM;

    const int SMEM = 3 * (128 + 256) * 64 * 2;   // 147456 B
    cudaFuncSetAttribute(gemm_h<0, __half>, cudaFuncAttributeMaxDynamicSharedMemorySize, SMEM);
    cudaFuncSetAttribute(gemm_h<1, __half>, cudaFuncAttributeMaxDynamicSharedMemorySize, SMEM);
    cudaFuncSetAttribute(gemm_h<2, __half>, cudaFuncAttributeMaxDynamicSharedMemorySize, SMEM);
    cudaFuncSetAttribute(gemm_h<3, __half>, cudaFuncAttributeMaxDynamicSharedMemorySize, SMEM);
    cudaFuncSetAttribute(gemm_h<4, float>,  cudaFuncAttributeMaxDynamicSharedMemorySize, SMEM);

    dim3 blk(256);
    dim3 g_thin(DIM / 256, N_TOK / 128);     // 2 x 64
    dim3 g_fat (N_TOK / 256, N_TOK / 128);   // 32 x 64
    dim3 g_vt  (N_TOK / 256, DIM / 128);     // 32 x 4

    // 1. prep: weight transposes + x conversion
    prep_k<<<5376, 256>>>(Wq, Wk, Wv, Wf, Wp, x, Wt, xh);
    // 2. Vt[d][n] = Wv^T row d . x row n + bv[d]  (row-bias)
    gemm_h<3, __half><<<g_vt, blk, SMEM>>>(Wvt, xh, bv, nullptr, nullptr, nullptr,
                                           Vt, DIM, N_TOK, DIM);
    // 3-4. Q/K projections
    gemm_h<0, __half><<<g_thin, blk, SMEM>>>(xh, Wqt, bq, nullptr, nullptr, nullptr,
                                             Q, N_TOK, DIM, DIM);
    gemm_h<0, __half><<<g_thin, blk, SMEM>>>(xh, Wkt, bk, nullptr, nullptr, nullptr,
                                             K, N_TOK, DIM, DIM);
    // 5. S = fp16( D .* (Q @ K^T) )
    gemm_h<2, __half><<<g_fat, blk, SMEM>>>(Q, K, nullptr, D, nullptr, nullptr,
                                            S, N_TOK, N_TOK, DIM);
    // 6. X = fp16( S @ V )  = S @ Vt^T   (this is launch #6 -> ncu captures it)
    gemm_h<0, __half><<<g_thin, blk, SMEM>>>(S, Vt, nullptr, nullptr, nullptr, nullptr,
                                             X, N_TOK, DIM, N_TOK);
    // 7. H = fp16( gelu(X @ Wf + bf) )
    gemm_h<1, __half><<<g_thin, blk, SMEM>>>(X, Wft, bf, nullptr, nullptr, nullptr,
                                             H, N_TOK, DIM, DIM);
    // 8. out = GroupNorm(H @ Wp + bp) fused
    gemm_h<4, float><<<g_thin, blk, SMEM>>>(H, Wpt, bp, nullptr, gamma, beta,
                                            out, N_TOK, DIM, DIM);
}

// round 8
// speedup vs baseline: 8.1019x; 1.0858x over previous
#include <cuda_runtime.h>
#include <cuda_fp16.h>
#include <math.h>
#include <stdint.h>

#define N_TOK 8192
#define DIM   512
#define GN_EPS 1e-5f

// ---------------- scratch (static device arrays; runtime alloc is forbidden) ----------------
__device__ __half g_Q [(size_t)N_TOK * DIM];
__device__ __half g_K [(size_t)N_TOK * DIM];
__device__ __half g_Vt[(size_t)N_TOK * DIM];         // V transposed [DIM][N_TOK]
__device__ __half g_S [(size_t)N_TOK * N_TOK];       // 128 MB retention matrix (fp16)
__device__ __half g_X [(size_t)N_TOK * DIM];
__device__ __half g_H [(size_t)N_TOK * DIM];
__device__ __half g_xh[(size_t)N_TOK * DIM];         // fp16 x
__device__ __half g_Wt[5 * (size_t)DIM * DIM];       // transposed fp16 weights

// ---------------- helpers ----------------
__device__ __forceinline__ uint32_t smem_u32(const void* p) {
    return (uint32_t)__cvta_generic_to_shared(p);
}
__device__ __forceinline__ void cpasync16(uint32_t dst, const void* src) {
    asm volatile("cp.async.cg.shared.global [%0], [%1], 16;" :: "r"(dst), "l"(src));
}
__device__ __forceinline__ void ldmatrix_x4(uint32_t& r0, uint32_t& r1, uint32_t& r2, uint32_t& r3,
                                            uint32_t addr) {
    asm volatile("ldmatrix.sync.aligned.m8n8.x4.shared.b16 {%0,%1,%2,%3}, [%4];"
                 : "=r"(r0), "=r"(r1), "=r"(r2), "=r"(r3) : "r"(addr));
}
__device__ __forceinline__ void mma_f16(float* c, const uint32_t* a, const uint32_t* b) {
    asm volatile("mma.sync.aligned.m16n8k16.row.col.f32.f16.f16.f32 "
                 "{%0,%1,%2,%3}, {%4,%5,%6,%7}, {%8,%9}, {%0,%1,%2,%3};"
                 : "+f"(c[0]), "+f"(c[1]), "+f"(c[2]), "+f"(c[3])
                 : "r"(a[0]), "r"(a[1]), "r"(a[2]), "r"(a[3]), "r"(b[0]), "r"(b[1]));
}

// ---------------- fp16 NT tensor-core GEMM ----------------
// C[M,Nn] = A[M,Kk] @ B^T, A/B are __half [.][Kk] row-major, fp32 accumulate.
// Block 128x128, 8 warps (2 M x 4 N), warp tile 64x32, BK=64 (128B rows, SW128 swizzle),
// 3-stage cp.async pipeline, 2 CTAs/SM for latency hiding.
// EPI: 0 = +bias[col] (may be null), 1 = gelu(c+bias[col]), 2 = c * Dm[row,col],
//      3 = +bias[row], 4 = bias[col] then fused GroupNorm (gamma/beta), fp32 out
template<int EPI, typename OutT>
__global__ __launch_bounds__(256, 2)
void gemm_h(const __half* __restrict__ A, const __half* __restrict__ B,
            const float* __restrict__ bias, const float* __restrict__ Dm,
            const float* __restrict__ gm, const float* __restrict__ bt,
            OutT* __restrict__ C, int M, int Nn, int Kk)
{
    constexpr int BM = 128, BN = 128, BK = 64, STAGES = 3;
    constexpr int A_BYTES = BM * BK * 2;          // 16384
    constexpr int B_BYTES = BN * BK * 2;          // 16384
    constexpr int STG_BYTES = A_BYTES + B_BYTES;  // 32768
    extern __shared__ char smem[];
    const uint32_t sbase = smem_u32(smem);

    const int t    = threadIdx.x;
    const int lane = t & 31;
    const int wid  = t >> 5;
    const int wm   = (wid & 1) * 64;              // 2 warps along M
    const int wn   = (wid >> 1) * 32;             // 4 warps along N
    const int br   = blockIdx.y;
    const int bc   = blockIdx.x;

    const int lr = t >> 3;                        // 0..31 (+32 per pass)
    const int lu = t & 7;                         // 16B unit in 128B row

    float acc[4][4][4];
    #pragma unroll
    for (int i = 0; i < 4; i++)
        #pragma unroll
        for (int j = 0; j < 4; j++)
            #pragma unroll
            for (int q = 0; q < 4; q++) acc[i][j][q] = 0.f;

    auto load_stage = [&](int it) {
        const uint32_t ab = sbase + (it % STAGES) * STG_BYTES;
        const uint32_t bb = ab + A_BYTES;
        const __half* Ag = A + (size_t)(br * BM) * Kk + it * BK;
        const __half* Bg = B + (size_t)(bc * BN) * Kk + it * BK;
        #pragma unroll
        for (int p = 0; p < 4; p++) {
            const int r = lr + p * 32;
            cpasync16(ab + r * 128 + ((lu ^ (r & 7)) << 4), Ag + (size_t)r * Kk + lu * 8);
        }
        #pragma unroll
        for (int p = 0; p < 4; p++) {
            const int r = lr + p * 32;
            cpasync16(bb + r * 128 + ((lu ^ (r & 7)) << 4), Bg + (size_t)r * Kk + lu * 8);
        }
        asm volatile("cp.async.commit_group;" ::: "memory");
    };

    auto compute_stage = [&](int it) {
        const uint32_t ab = sbase + (it % STAGES) * STG_BYTES;
        const uint32_t bb = ab + A_BYTES;
        const int j  = lane >> 3;                 // 0..3
        const int rr = lane & 7;
        #pragma unroll
        for (int ks = 0; ks < 4; ks++) {          // 4 x k16 steps = BK=64
            const int ub = ks * 2;                // base 16B-unit
            uint32_t af[4][4];
            #pragma unroll
            for (int mf = 0; mf < 4; mf++) {
                const int row  = wm + mf * 16 + (j & 1) * 8 + rr;
                const int unit = ub + (j >> 1);
                ldmatrix_x4(af[mf][0], af[mf][1], af[mf][2], af[mf][3],
                            ab + row * 128 + ((unit ^ (row & 7)) << 4));
            }
            uint32_t bf[4][2];
            #pragma unroll
            for (int nb = 0; nb < 2; nb++) {
                const int row  = wn + nb * 16 + (j >> 1) * 8 + rr;
                const int unit = ub + (j & 1);
                uint32_t r0, r1, r2, r3;
                ldmatrix_x4(r0, r1, r2, r3, bb + row * 128 + ((unit ^ (row & 7)) << 4));
                bf[nb * 2 + 0][0] = r0; bf[nb * 2 + 0][1] = r1;
                bf[nb * 2 + 1][0] = r2; bf[nb * 2 + 1][1] = r3;
            }
            #pragma unroll
            for (int mf = 0; mf < 4; mf++)
                #pragma unroll
                for (int nf = 0; nf < 4; nf++)
                    mma_f16(acc[mf][nf], af[mf], bf[nf]);
        }
    };

    const int nk = Kk / BK;
    load_stage(0);
    load_stage(1);
    for (int it = 0; it < nk; it++) {
        if (it + 1 < nk) asm volatile("cp.async.wait_group 1;" ::: "memory");
        else             asm volatile("cp.async.wait_group 0;" ::: "memory");
        __syncthreads();
        if (it + 2 < nk) load_stage(it + 2);
        compute_stage(it);
    }

    // ---- epilogue ----
    const int g = lane >> 2, tg = lane & 3;

    if (EPI == 4) {
        // bias[col] + fused GroupNorm. Warp covers 32 cols == exactly one group;
        // per row, the 32 group values live in the 4 lanes sharing g (tg=0..3),
        // 8 values each -> quad shfl reduce.
        #pragma unroll
        for (int mf = 0; mf < 4; mf++) {
            #pragma unroll
            for (int h = 0; h < 2; h++) {
                const int row = br * BM + wm + mf * 16 + g + h * 8;
                float v[8];
                #pragma unroll
                for (int nf = 0; nf < 4; nf++) {
                    const int col = bc * BN + wn + nf * 8 + tg * 2;
                    v[nf * 2 + 0] = acc[mf][nf][h * 2 + 0] + bias[col];
                    v[nf * 2 + 1] = acc[mf][nf][h * 2 + 1] + bias[col + 1];
                }
                float s = 0.f, s2 = 0.f;
                #pragma unroll
                for (int q = 0; q < 8; q++) { s += v[q]; s2 += v[q] * v[q]; }
                s  += __shfl_xor_sync(0xffffffffu, s, 1);
                s  += __shfl_xor_sync(0xffffffffu, s, 2);
                s2 += __shfl_xor_sync(0xffffffffu, s2, 1);
                s2 += __shfl_xor_sync(0xffffffffu, s2, 2);
                const float mu  = s * (1.f / 32.f);
                const float var = s2 * (1.f / 32.f) - mu * mu;
                const float inv = rsqrtf(var + GN_EPS);
                #pragma unroll
                for (int nf = 0; nf < 4; nf++) {
                    const int col = bc * BN + wn + nf * 8 + tg * 2;
                    float c0 = (v[nf * 2 + 0] - mu) * inv * gm[col]     + bt[col];
                    float c1 = (v[nf * 2 + 1] - mu) * inv * gm[col + 1] + bt[col + 1];
                    float2 o = { c0, c1 };
                    *(float2*)((float*)C + (size_t)row * Nn + col) = o;
                }
            }
        }
        return;
    }

    #pragma unroll
    for (int mf = 0; mf < 4; mf++) {
        #pragma unroll
        for (int nf = 0; nf < 4; nf++) {
            const int col = bc * BN + wn + nf * 8 + tg * 2;
            #pragma unroll
            for (int h = 0; h < 2; h++) {
                const int row = br * BM + wm + mf * 16 + g + h * 8;
                float c0 = acc[mf][nf][h * 2 + 0];
                float c1 = acc[mf][nf][h * 2 + 1];
                if (EPI == 2) {
                    const float2 d = *(const float2*)(Dm + (size_t)row * Nn + col);
                    c0 *= d.x; c1 *= d.y;
                } else if (EPI == 3) {
                    const float b = bias[row];
                    c0 += b; c1 += b;
                } else {
                    if (bias) { c0 += bias[col]; c1 += bias[col + 1]; }
                    if (EPI == 1) {
                        c0 = 0.5f * c0 * (1.f + erff(c0 * 0.70710678118654752f));
                        c1 = 0.5f * c1 * (1.f + erff(c1 * 0.70710678118654752f));
                    }
                }
                OutT* Cp = C + (size_t)row * Nn + col;
                if (sizeof(OutT) == 2) {
                    __half2 o = __floats2half2_rn(c0, c1);
                    *(__half2*)Cp = o;
                } else {
                    float2 o = { c0, c1 };
                    *(float2*)Cp = o;
                }
            }
        }
    }
}

// ---------------- fused prep: 5 weight transposes (fp32->fp16) + x fp32->fp16 ----------------
__global__ void prep_k(const float* __restrict__ Wq, const float* __restrict__ Wk,
                       const float* __restrict__ Wv, const float* __restrict__ Wf,
                       const float* __restrict__ Wp, const float* __restrict__ x,
                       __half* __restrict__ Wt, __half* __restrict__ xh)
{
    const int b = blockIdx.x;
    const int t = threadIdx.x;
    if (b < 1280) {
        __shared__ float tile[32][33];
        const int w  = b >> 8;                   // weight index 0..4
        const int ti = b & 255;
        const int bx = ti & 15, by = ti >> 4;
        const float* in = (w == 0) ? Wq : (w == 1) ? Wk : (w == 2) ? Wv : (w == 3) ? Wf : Wp;
        __half* out = Wt + (size_t)w * DIM * DIM;
        const int tx = t & 31, tyb = t >> 5;     // 32 x 8
        int x0 = bx * 32 + tx;
        #pragma unroll
        for (int i = 0; i < 32; i += 8)
            tile[tyb + i][tx] = in[(size_t)(by * 32 + tyb + i) * DIM + x0];
        __syncthreads();
        int x1 = by * 32 + tx;
        #pragma unroll
        for (int i = 0; i < 32; i += 8)
            out[(size_t)(bx * 32 + tyb + i) * DIM + x1] = __float2half_rn(tile[tx][tyb + i]);
    } else {
        const int i = (b - 1280) * 256 + t;      // < 1048576
        float4 v = ((const float4*)x)[i];
        __half2 a = __floats2half2_rn(v.x, v.y);
        __half2 c = __floats2half2_rn(v.z, v.w);
        uint2 o = { *(uint32_t*)&a, *(uint32_t*)&c };
        ((uint2*)xh)[i] = o;
    }
}

// ---------------- launch ----------------
extern "C" void kernel_launch(void* const* d_in, const int* in_sizes, int n_in,
                              void* d_out, int out_size)
{
    const float* x     = (const float*)d_in[0];
    const float* D     = (const float*)d_in[1];
    const float* Wq    = (const float*)d_in[2];
    const float* bq    = (const float*)d_in[3];
    const float* Wk    = (const float*)d_in[4];
    const float* bk    = (const float*)d_in[5];
    const float* Wv    = (const float*)d_in[6];
    const float* bv    = (const float*)d_in[7];
    const float* Wf    = (const float*)d_in[8];
    const float* bf    = (const float*)d_in[9];
    const float* Wp    = (const float*)d_in[10];
    const float* bp    = (const float*)d_in[11];
    const float* gamma = (const float*)d_in[12];
    const float* beta  = (const float*)d_in[13];
    float* out = (float*)d_out;

    __half *Q, *K, *Vt, *S, *X, *H, *xh, *Wt;
    cudaGetSymbolAddress((void**)&Q,  g_Q);
    cudaGetSymbolAddress((void**)&K,  g_K);
    cudaGetSymbolAddress((void**)&Vt, g_Vt);
    cudaGetSymbolAddress((void**)&S,  g_S);
    cudaGetSymbolAddress((void**)&X,  g_X);
    cudaGetSymbolAddress((void**)&H,  g_H);
    cudaGetSymbolAddress((void**)&xh, g_xh);
    cudaGetSymbolAddress((void**)&Wt, g_Wt);

    __half* Wqt = Wt + 0 * (size_t)DIM * DIM;
    __half* Wkt = Wt + 1 * (size_t)DIM * DIM;
    __half* Wvt = Wt + 2 * (size_t)DIM * DIM;
    __half* Wft = Wt + 3 * (size_t)DIM * DIM;
    __half* Wpt = Wt + 4 * (size_t)DIM * DIM;

    const int SMEM = 3 * (128 + 128) * 64 * 2;   // 98304 B
    cudaFuncSetAttribute(gemm_h<0, __half>, cudaFuncAttributeMaxDynamicSharedMemorySize, SMEM);
    cudaFuncSetAttribute(gemm_h<1, __half>, cudaFuncAttributeMaxDynamicSharedMemorySize, SMEM);
    cudaFuncSetAttribute(gemm_h<2, __half>, cudaFuncAttributeMaxDynamicSharedMemorySize, SMEM);
    cudaFuncSetAttribute(gemm_h<3, __half>, cudaFuncAttributeMaxDynamicSharedMemorySize, SMEM);
    cudaFuncSetAttribute(gemm_h<4, float>,  cudaFuncAttributeMaxDynamicSharedMemorySize, SMEM);

    dim3 blk(256);
    dim3 g_thin(DIM / 128, N_TOK / 128);     // 4 x 64 = 256
    dim3 g_fat (N_TOK / 128, N_TOK / 128);   // 64 x 64 = 4096
    dim3 g_vt  (N_TOK / 128, DIM / 128);     // 64 x 4  = 256

    // 1. prep: weight transposes + x conversion
    prep_k<<<5376, 256>>>(Wq, Wk, Wv, Wf, Wp, x, Wt, xh);
    // 2. Vt[d][n] = Wv^T row d . x row n + bv[d]  (row-bias)
    gemm_h<3, __half><<<g_vt, blk, SMEM>>>(Wvt, xh, bv, nullptr, nullptr, nullptr,
                                           Vt, DIM, N_TOK, DIM);
    // 3-4. Q/K projections
    gemm_h<0, __half><<<g_thin, blk, SMEM>>>(xh, Wqt, bq, nullptr, nullptr, nullptr,
                                             Q, N_TOK, DIM, DIM);
    gemm_h<0, __half><<<g_thin, blk, SMEM>>>(xh, Wkt, bk, nullptr, nullptr, nullptr,
                                             K, N_TOK, DIM, DIM);
    // 5. S = fp16( D .* (Q @ K^T) )
    gemm_h<2, __half><<<g_fat, blk, SMEM>>>(Q, K, nullptr, D, nullptr, nullptr,
                                            S, N_TOK, N_TOK, DIM);
    // 6. X = fp16( S @ V ) = S @ Vt^T   (launch #6 -> ncu captures it)
    gemm_h<0, __half><<<g_thin, blk, SMEM>>>(S, Vt, nullptr, nullptr, nullptr, nullptr,
                                             X, N_TOK, DIM, N_TOK);
    // 7. H = fp16( gelu(X @ Wf + bf) )
    gemm_h<1, __half><<<g_thin, blk, SMEM>>>(X, Wft, bf, nullptr, nullptr, nullptr,
                                             H, N_TOK, DIM, DIM);
    // 8. out = GroupNorm(H @ Wp + bp) fused
    gemm_h<4, float><<<g_thin, blk, SMEM>>>(H, Wpt, bp, nullptr, gamma, beta,
                                            out, N_TOK, DIM, DIM);
}